// round 1
// baseline (speedup 1.0000x reference)
#include <cuda_runtime.h>
#include <cstdint>

#define NNODES 50000
#define NEDGES 600000
#define HC 128
#define NH 4
#define CDIM 32

// ---------------- scratch (device globals; no allocation allowed) ----------------
__device__ float g_x[NNODES * HC];      // current node features (updated per layer)
__device__ float g_h[NNODES * HC];      // h = x @ W + linb
__device__ float g_skip[NNODES * HC];   // skip = x @ sW + sb (layer 2 uses stride 32)
__device__ float g_score[NEDGES * NH];  // per-edge scores, then exp(p)
__device__ float g_m[NNODES * NH];      // segment max
__device__ float g_denom[NNODES * NH];  // segment sum of p
__device__ float g_agg[NNODES * HC];    // attention-weighted aggregation
__device__ int   g_src[NEDGES];
__device__ int   g_dst[NEDGES];
__device__ int   g_is64;

// ---------------- edge_index dtype detection + decode ----------------
// If the buffer is int64 (little endian, values < 2^32), every odd 32-bit word is 0.
__global__ void detect_kernel(const unsigned int* __restrict__ buf) {
    __shared__ int nz;
    if (threadIdx.x == 0) nz = 0;
    __syncthreads();
    if (buf[2 * threadIdx.x + 1] != 0u) atomicOr(&nz, 1);
    __syncthreads();
    if (threadIdx.x == 0) g_is64 = (nz == 0) ? 1 : 0;
}

__global__ void decode_kernel(const void* __restrict__ buf) {
    int i = blockIdx.x * blockDim.x + threadIdx.x;
    if (i >= 2 * NEDGES) return;
    int v;
    if (g_is64) v = (int)(((const long long*)buf)[i]);
    else        v = ((const int*)buf)[i];
    if (i < NEDGES) g_src[i] = v;
    else            g_dst[i - NEDGES] = v;
}

// ---------------- SGEMM: C[M x NNo] = A[M x 128] @ B[128 x NNo] + bias ----------------
// 64x64 block tile, K-chunks of 32, 4x4 register micro-tile per thread (16x16 threads).
#define BM 64
#define BN 64
#define BK 32

__global__ __launch_bounds__(256) void gemm_kernel(
    const float* __restrict__ A_ext, int useGX,
    const float* __restrict__ B, const float* __restrict__ bias,
    int M, int NNo, int target /* 0 -> g_h, 1 -> g_skip */) {

    __shared__ float As[BM][BK];
    __shared__ float Bs[BK][BN];

    const float* A = useGX ? g_x : A_ext;
    float* C = target ? g_skip : g_h;

    int tid = threadIdx.x;
    int tx = tid & 15;
    int ty = tid >> 4;
    int m0 = blockIdx.y * BM;
    int n0 = blockIdx.x * BN;

    float acc[4][4];
#pragma unroll
    for (int i = 0; i < 4; i++)
#pragma unroll
        for (int j = 0; j < 4; j++) acc[i][j] = 0.f;

    for (int kc = 0; kc < 128; kc += BK) {
        // load A tile: 64 rows x 32 k -> 512 float4, 2 per thread
#pragma unroll
        for (int q = 0; q < 2; q++) {
            int f = tid + q * 256;
            int row = f >> 3;       // 0..63
            int kq  = f & 7;        // 0..7 (float4 within 32 k)
            float4 v = make_float4(0.f, 0.f, 0.f, 0.f);
            if (m0 + row < M)
                v = *(const float4*)(A + (size_t)(m0 + row) * 128 + kc + 4 * kq);
            *(float4*)&As[row][4 * kq] = v;
        }
        // load B tile: 32 k rows x 64 cols -> 512 float4, 2 per thread
#pragma unroll
        for (int q = 0; q < 2; q++) {
            int f = tid + q * 256;
            int kr = f >> 4;        // 0..31
            int cq = f & 15;        // 0..15 (float4 within 64 cols)
            float4 v = make_float4(0.f, 0.f, 0.f, 0.f);
            int col = n0 + 4 * cq;
            if (col < NNo)
                v = *(const float4*)(B + (size_t)(kc + kr) * NNo + col);
            *(float4*)&Bs[kr][4 * cq] = v;
        }
        __syncthreads();

#pragma unroll
        for (int k = 0; k < BK; k++) {
            float4 b4 = *(const float4*)&Bs[k][4 * tx];
            float a0 = As[4 * ty + 0][k];
            float a1 = As[4 * ty + 1][k];
            float a2 = As[4 * ty + 2][k];
            float a3 = As[4 * ty + 3][k];
            acc[0][0] += a0 * b4.x; acc[0][1] += a0 * b4.y; acc[0][2] += a0 * b4.z; acc[0][3] += a0 * b4.w;
            acc[1][0] += a1 * b4.x; acc[1][1] += a1 * b4.y; acc[1][2] += a1 * b4.z; acc[1][3] += a1 * b4.w;
            acc[2][0] += a2 * b4.x; acc[2][1] += a2 * b4.y; acc[2][2] += a2 * b4.z; acc[2][3] += a2 * b4.w;
            acc[3][0] += a3 * b4.x; acc[3][1] += a3 * b4.y; acc[3][2] += a3 * b4.z; acc[3][3] += a3 * b4.w;
        }
        __syncthreads();
    }

    int col = n0 + 4 * tx;
    if (col < NNo) {
        float4 b4 = *(const float4*)(bias + col);
#pragma unroll
        for (int i = 0; i < 4; i++) {
            int row = m0 + 4 * ty + i;
            if (row < M) {
                float4 o = make_float4(acc[i][0] + b4.x, acc[i][1] + b4.y,
                                       acc[i][2] + b4.z, acc[i][3] + b4.w);
                *(float4*)(C + (size_t)row * NNo + col) = o;
            }
        }
    }
}

// ---------------- per-layer init ----------------
__global__ void init_kernel() {
    int i = blockIdx.x * blockDim.x + threadIdx.x;
    if (i < NNODES * NH) {
        g_m[i] = __int_as_float(0xff800000); // -inf
        g_denom[i] = 0.f;
    }
    if (i < NNODES * HC) g_agg[i] = 0.f;
}

// ---------------- float atomic max (sign-aware) ----------------
__device__ __forceinline__ void atomicMaxF(float* a, float v) {
    unsigned int bits = __float_as_uint(v);
    if ((bits >> 31) == 0u) atomicMax((int*)a, (int)bits);          // v >= +0
    else                    atomicMin((unsigned int*)a, bits);      // v <= -0
}

// ---------------- pass 1: score + segment max (warp per edge) ----------------
__global__ __launch_bounds__(256) void score_kernel(const float* __restrict__ att) {
    int gw = (blockIdx.x * blockDim.x + threadIdx.x) >> 5;
    int lane = threadIdx.x & 31;
    if (gw >= NEDGES) return;
    int s = g_src[gw], d = g_dst[gw];
    const float* hs = g_h + (size_t)s * HC;
    const float* hd = g_h + (size_t)d * HC;
    float sc[NH];
#pragma unroll
    for (int h = 0; h < NH; h++) {
        float v = hs[h * 32 + lane] + hd[h * 32 + lane];
        v = v > 0.f ? v : 0.2f * v;        // leaky relu
        sc[h] = v * __ldg(att + h * 32 + lane);
    }
#pragma unroll
    for (int off = 16; off; off >>= 1) {
#pragma unroll
        for (int h = 0; h < NH; h++) sc[h] += __shfl_xor_sync(0xffffffffu, sc[h], off);
    }
    if (lane == 0) {
        *(float4*)&g_score[gw * 4] = make_float4(sc[0], sc[1], sc[2], sc[3]);
#pragma unroll
        for (int h = 0; h < NH; h++) atomicMaxF(&g_m[d * 4 + h], sc[h]);
    }
}

// ---------------- pass 2: p = exp(score - m[dst]); denom += p ----------------
__global__ __launch_bounds__(256) void p_kernel() {
    int e = blockIdx.x * blockDim.x + threadIdx.x;
    if (e >= NEDGES) return;
    int d = g_dst[e];
    float4 sc = *(const float4*)&g_score[e * 4];
    float4 mm = *(const float4*)&g_m[d * 4];
    float4 p = make_float4(__expf(sc.x - mm.x), __expf(sc.y - mm.y),
                           __expf(sc.z - mm.z), __expf(sc.w - mm.w));
    *(float4*)&g_score[e * 4] = p;
    atomicAdd((float4*)&g_denom[d * 4], p);
}

// ---------------- pass 3: agg[dst] += alpha * h[src] (warp per edge) ----------------
__global__ __launch_bounds__(256) void agg_kernel() {
    int gw = (blockIdx.x * blockDim.x + threadIdx.x) >> 5;
    int lane = threadIdx.x & 31;
    if (gw >= NEDGES) return;
    int s = g_src[gw], d = g_dst[gw];
    float4 p  = *(const float4*)&g_score[gw * 4];
    float4 dn = *(const float4*)&g_denom[d * 4];
    float al[NH] = { p.x / fmaxf(dn.x, 1e-16f), p.y / fmaxf(dn.y, 1e-16f),
                     p.z / fmaxf(dn.z, 1e-16f), p.w / fmaxf(dn.w, 1e-16f) };
    float a = al[lane >> 3];                    // lane l covers floats [4l,4l+4) -> head l/8
    float4 v = *(const float4*)(g_h + (size_t)s * HC + 4 * lane);
    v.x *= a; v.y *= a; v.z *= a; v.w *= a;
    atomicAdd((float4*)(g_agg + (size_t)d * HC) + lane, v);
}

// ---------------- combine (layers 0,1): x = elu(agg + bias + skip) ----------------
__global__ void combine_kernel(const float* __restrict__ bias) {
    int i = blockIdx.x * blockDim.x + threadIdx.x;
    if (i >= NNODES * HC) return;
    float v = g_agg[i] + __ldg(bias + (i & 127)) + g_skip[i];
    g_x[i] = v > 0.f ? v : expm1f(v);
}

// ---------------- final (layer 2): out = mean_h(agg) + bias + skip ----------------
__global__ void final_kernel(const float* __restrict__ bias, float* __restrict__ out) {
    int i = blockIdx.x * blockDim.x + threadIdx.x;
    if (i >= NNODES * CDIM) return;
    int n = i >> 5, c = i & 31;
    const float* a = g_agg + (size_t)n * HC;
    float v = 0.25f * (a[c] + a[32 + c] + a[64 + c] + a[96 + c])
            + __ldg(bias + c) + g_skip[i];
    out[i] = v;
}

// ---------------- launch ----------------
extern "C" void kernel_launch(void* const* d_in, const int* in_sizes, int n_in,
                              void* d_out, int out_size) {
    const float* x  = (const float*)d_in[0];
    const void*  ei = d_in[1];
    const float* W[3]    = {(const float*)d_in[2],  (const float*)d_in[8],  (const float*)d_in[14]};
    const float* linb[3] = {(const float*)d_in[3],  (const float*)d_in[9],  (const float*)d_in[15]};
    const float* att[3]  = {(const float*)d_in[4],  (const float*)d_in[10], (const float*)d_in[16]};
    const float* bias[3] = {(const float*)d_in[5],  (const float*)d_in[11], (const float*)d_in[17]};
    const float* sW[3]   = {(const float*)d_in[6],  (const float*)d_in[12], (const float*)d_in[18]};
    const float* sb[3]   = {(const float*)d_in[7],  (const float*)d_in[13], (const float*)d_in[19]};

    detect_kernel<<<1, 256>>>((const unsigned int*)ei);
    decode_kernel<<<(2 * NEDGES + 255) / 256, 256>>>(ei);

    const int M = NNODES;
    dim3 gemm_grid128(2, (M + BM - 1) / BM);
    dim3 gemm_grid32(1, (M + BM - 1) / BM);

    int init_blocks  = (NNODES * HC + 255) / 256;
    int warp_blocks  = (NEDGES * 32 + 255) / 256;
    int edge_blocks  = (NEDGES + 255) / 256;
    int comb_blocks  = (NNODES * HC + 255) / 256;
    int final_blocks = (NNODES * CDIM + 255) / 256;

    for (int l = 0; l < 3; l++) {
        int useGX = (l > 0) ? 1 : 0;
        int skipN = (l < 2) ? 128 : 32;

        // h = A @ W + linb  (128 wide)
        gemm_kernel<<<gemm_grid128, 256>>>(x, useGX, W[l], linb[l], M, 128, 0);
        // skip = A @ sW + sb (128 or 32 wide)
        gemm_kernel<<<(skipN == 128 ? gemm_grid128 : gemm_grid32), 256>>>(
            x, useGX, sW[l], sb[l], M, skipN, 1);

        init_kernel<<<init_blocks, 256>>>();
        score_kernel<<<warp_blocks, 256>>>(att[l]);
        p_kernel<<<edge_blocks, 256>>>();
        agg_kernel<<<warp_blocks, 256>>>();

        if (l < 2) combine_kernel<<<comb_blocks, 256>>>(bias[l]);
        else       final_kernel<<<final_blocks, 256>>>(bias[l], (float*)d_out);
    }
}

// round 2
// speedup vs baseline: 1.9503x; 1.9503x over previous
#include <cuda_runtime.h>
#include <cstdint>

#define NNODES 50000
#define NEDGES 600000
#define HC 128
#define NH 4
#define CDIM 32
#define SCAN_BLOCKS ((NNODES + 255) / 256)   // 196

// ---------------- scratch (device globals; no allocation allowed) ----------------
__device__ float g_x[NNODES * HC];      // current node features (updated per layer)
__device__ float g_h[NNODES * HC];      // h = x @ W + linb
__device__ float g_skip[NNODES * HC];   // skip = x @ sW + sb (layer 2 uses stride 32)
__device__ int   g_src[NEDGES];
__device__ int   g_dst[NEDGES];
__device__ int   g_deg[NNODES];
__device__ int   g_rowptr[NNODES + 1];
__device__ int   g_ptr[NNODES];
__device__ int   g_bsum[SCAN_BLOCKS];
__device__ int   g_csr_src[NEDGES];
__device__ int   g_is64;

// ---------------- edge_index dtype detection + decode ----------------
__global__ void detect_kernel(const unsigned int* __restrict__ buf) {
    __shared__ int nz;
    if (threadIdx.x == 0) nz = 0;
    __syncthreads();
    if (buf[2 * threadIdx.x + 1] != 0u) atomicOr(&nz, 1);
    __syncthreads();
    if (threadIdx.x == 0) g_is64 = (nz == 0) ? 1 : 0;
}

__global__ void decode_kernel(const void* __restrict__ buf) {
    int i = blockIdx.x * blockDim.x + threadIdx.x;
    if (i >= 2 * NEDGES) return;
    int v;
    if (g_is64) v = (int)(((const long long*)buf)[i]);
    else        v = ((const int*)buf)[i];
    if (i < NEDGES) g_src[i] = v;
    else            g_dst[i - NEDGES] = v;
}

// ---------------- CSR build ----------------
__global__ void zero_deg_kernel() {
    int i = blockIdx.x * blockDim.x + threadIdx.x;
    if (i < NNODES) g_deg[i] = 0;
}

__global__ void hist_kernel() {
    int e = blockIdx.x * blockDim.x + threadIdx.x;
    if (e < NEDGES) atomicAdd(&g_deg[g_dst[e]], 1);
}

__global__ void scan1_kernel() {
    __shared__ int sh[256];
    int i = blockIdx.x * 256 + threadIdx.x;
    int v = (i < NNODES) ? g_deg[i] : 0;
    sh[threadIdx.x] = v;
    __syncthreads();
#pragma unroll
    for (int off = 1; off < 256; off <<= 1) {
        int t = (threadIdx.x >= off) ? sh[threadIdx.x - off] : 0;
        __syncthreads();
        sh[threadIdx.x] += t;
        __syncthreads();
    }
    if (i < NNODES) g_rowptr[i + 1] = sh[threadIdx.x];
    if (threadIdx.x == 255) g_bsum[blockIdx.x] = sh[255];
}

__global__ void scan2_kernel() {
    __shared__ int sh[256];
    int v = (threadIdx.x < SCAN_BLOCKS) ? g_bsum[threadIdx.x] : 0;
    sh[threadIdx.x] = v;
    __syncthreads();
#pragma unroll
    for (int off = 1; off < 256; off <<= 1) {
        int t = (threadIdx.x >= off) ? sh[threadIdx.x - off] : 0;
        __syncthreads();
        sh[threadIdx.x] += t;
        __syncthreads();
    }
    if (threadIdx.x < SCAN_BLOCKS)
        g_bsum[threadIdx.x] = (threadIdx.x == 0) ? 0 : sh[threadIdx.x - 1];
}

__global__ void scan3_kernel() {
    int i = blockIdx.x * blockDim.x + threadIdx.x;
    if (i == 0) g_rowptr[0] = 0;
    if (i < NNODES) g_rowptr[i + 1] += g_bsum[i >> 8];
}

__global__ void copyptr_kernel() {
    int i = blockIdx.x * blockDim.x + threadIdx.x;
    if (i < NNODES) g_ptr[i] = g_rowptr[i];
}

__global__ void scatter_kernel() {
    int e = blockIdx.x * blockDim.x + threadIdx.x;
    if (e >= NEDGES) return;
    int d = g_dst[e];
    int pos = atomicAdd(&g_ptr[d], 1);
    g_csr_src[pos] = g_src[e];
}

// ---------------- SGEMM: C[M x NNo] = A[M x 128] @ B[128 x NNo] + bias ----------------
#define BM 64
#define BN 64
#define BK 32

__global__ __launch_bounds__(256) void gemm_kernel(
    const float* __restrict__ A_ext, int useGX,
    const float* __restrict__ B, const float* __restrict__ bias,
    int M, int NNo, int target /* 0 -> g_h, 1 -> g_skip */) {

    __shared__ float As[BM][BK];
    __shared__ float Bs[BK][BN];

    const float* A = useGX ? g_x : A_ext;
    float* C = target ? g_skip : g_h;

    int tid = threadIdx.x;
    int tx = tid & 15;
    int ty = tid >> 4;
    int m0 = blockIdx.y * BM;
    int n0 = blockIdx.x * BN;

    float acc[4][4];
#pragma unroll
    for (int i = 0; i < 4; i++)
#pragma unroll
        for (int j = 0; j < 4; j++) acc[i][j] = 0.f;

    for (int kc = 0; kc < 128; kc += BK) {
#pragma unroll
        for (int q = 0; q < 2; q++) {
            int f = tid + q * 256;
            int row = f >> 3;
            int kq  = f & 7;
            float4 v = make_float4(0.f, 0.f, 0.f, 0.f);
            if (m0 + row < M)
                v = *(const float4*)(A + (size_t)(m0 + row) * 128 + kc + 4 * kq);
            *(float4*)&As[row][4 * kq] = v;
        }
#pragma unroll
        for (int q = 0; q < 2; q++) {
            int f = tid + q * 256;
            int kr = f >> 4;
            int cq = f & 15;
            float4 v = make_float4(0.f, 0.f, 0.f, 0.f);
            int col = n0 + 4 * cq;
            if (col < NNo)
                v = *(const float4*)(B + (size_t)(kc + kr) * NNo + col);
            *(float4*)&Bs[kr][4 * cq] = v;
        }
        __syncthreads();

#pragma unroll
        for (int k = 0; k < BK; k++) {
            float4 b4 = *(const float4*)&Bs[k][4 * tx];
            float a0 = As[4 * ty + 0][k];
            float a1 = As[4 * ty + 1][k];
            float a2 = As[4 * ty + 2][k];
            float a3 = As[4 * ty + 3][k];
            acc[0][0] += a0 * b4.x; acc[0][1] += a0 * b4.y; acc[0][2] += a0 * b4.z; acc[0][3] += a0 * b4.w;
            acc[1][0] += a1 * b4.x; acc[1][1] += a1 * b4.y; acc[1][2] += a1 * b4.z; acc[1][3] += a1 * b4.w;
            acc[2][0] += a2 * b4.x; acc[2][1] += a2 * b4.y; acc[2][2] += a2 * b4.z; acc[2][3] += a2 * b4.w;
            acc[3][0] += a3 * b4.x; acc[3][1] += a3 * b4.y; acc[3][2] += a3 * b4.z; acc[3][3] += a3 * b4.w;
        }
        __syncthreads();
    }

    int col = n0 + 4 * tx;
    if (col < NNo) {
        float4 b4 = *(const float4*)(bias + col);
#pragma unroll
        for (int i = 0; i < 4; i++) {
            int row = m0 + 4 * ty + i;
            if (row < M) {
                float4 o = make_float4(acc[i][0] + b4.x, acc[i][1] + b4.y,
                                       acc[i][2] + b4.z, acc[i][3] + b4.w);
                *(float4*)(C + (size_t)row * NNo + col) = o;
            }
        }
    }
}

// ---------------- fused attention: online softmax, warp per dst node ----------------
// lane covers channels [4*lane, 4*lane+4); head = lane>>3 (8 lanes x 4 ch = 32 ch/head)
__device__ __forceinline__ float lrelu(float v) {
    return fmaxf(v, 0.f) + 0.2f * fminf(v, 0.f);
}

__global__ __launch_bounds__(256) void attn_kernel(
    const float* __restrict__ att, const float* __restrict__ bias,
    int last, float* __restrict__ out) {

    int gw = (blockIdx.x * blockDim.x + threadIdx.x) >> 5;
    int lane = threadIdx.x & 31;
    if (gw >= NNODES) return;
    int n = gw;

    float4 att4 = ((const float4*)att)[lane];
    float4 hd4  = ((const float4*)(g_h + (size_t)n * HC))[lane];

    float m = __int_as_float(0xff800000);   // -inf
    float denom = 0.f;
    float4 acc = make_float4(0.f, 0.f, 0.f, 0.f);

    int start = g_rowptr[n];
    int end   = g_rowptr[n + 1];

    for (int base = start; base < end; base += 32) {
        int cnt = min(32, end - base);
        int sidx = (lane < cnt) ? g_csr_src[base + lane] : 0;
        for (int e = 0; e < cnt; e++) {
            int s = __shfl_sync(0xffffffffu, sidx, e);
            float4 hs4 = *((const float4*)(g_h + (size_t)s * HC) + lane);

            float part = lrelu(hs4.x + hd4.x) * att4.x
                       + lrelu(hs4.y + hd4.y) * att4.y
                       + lrelu(hs4.z + hd4.z) * att4.z
                       + lrelu(hs4.w + hd4.w) * att4.w;
            part += __shfl_xor_sync(0xffffffffu, part, 1);
            part += __shfl_xor_sync(0xffffffffu, part, 2);
            part += __shfl_xor_sync(0xffffffffu, part, 4);
            // part = score for this edge's head (same in all 8 lanes of the group)

            float mn = fmaxf(m, part);
            float scale = __expf(m - mn);     // 0 when m = -inf
            float p = __expf(part - mn);
            denom = denom * scale + p;
            acc.x = acc.x * scale + p * hs4.x;
            acc.y = acc.y * scale + p * hs4.y;
            acc.z = acc.z * scale + p * hs4.z;
            acc.w = acc.w * scale + p * hs4.w;
            m = mn;
        }
    }

    float inv = 1.0f / fmaxf(denom, 1e-16f);

    if (!last) {
        float4 sk = ((const float4*)(g_skip + (size_t)n * HC))[lane];
        float4 b4 = ((const float4*)bias)[lane];
        float4 o;
        o.x = acc.x * inv + b4.x + sk.x;
        o.y = acc.y * inv + b4.y + sk.y;
        o.z = acc.z * inv + b4.z + sk.z;
        o.w = acc.w * inv + b4.w + sk.w;
        o.x = o.x > 0.f ? o.x : expm1f(o.x);
        o.y = o.y > 0.f ? o.y : expm1f(o.y);
        o.z = o.z > 0.f ? o.z : expm1f(o.z);
        o.w = o.w > 0.f ? o.w : expm1f(o.w);
        ((float4*)(g_x + (size_t)n * HC))[lane] = o;
    } else {
        float4 r;
        r.x = acc.x * inv; r.y = acc.y * inv; r.z = acc.z * inv; r.w = acc.w * inv;
        // mean over 4 heads: reduce lanes differing by 8 and 16
        r.x += __shfl_xor_sync(0xffffffffu, r.x, 8);
        r.y += __shfl_xor_sync(0xffffffffu, r.y, 8);
        r.z += __shfl_xor_sync(0xffffffffu, r.z, 8);
        r.w += __shfl_xor_sync(0xffffffffu, r.w, 8);
        r.x += __shfl_xor_sync(0xffffffffu, r.x, 16);
        r.y += __shfl_xor_sync(0xffffffffu, r.y, 16);
        r.z += __shfl_xor_sync(0xffffffffu, r.z, 16);
        r.w += __shfl_xor_sync(0xffffffffu, r.w, 16);
        if (lane < 8) {
            float4 sk = ((const float4*)(g_skip + (size_t)n * CDIM))[lane];
            float4 b4 = ((const float4*)bias)[lane];
            float4 o;
            o.x = 0.25f * r.x + b4.x + sk.x;
            o.y = 0.25f * r.y + b4.y + sk.y;
            o.z = 0.25f * r.z + b4.z + sk.z;
            o.w = 0.25f * r.w + b4.w + sk.w;
            ((float4*)(out + (size_t)n * CDIM))[lane] = o;
        }
    }
}

// ---------------- launch ----------------
extern "C" void kernel_launch(void* const* d_in, const int* in_sizes, int n_in,
                              void* d_out, int out_size) {
    const float* x  = (const float*)d_in[0];
    const void*  ei = d_in[1];
    const float* W[3]    = {(const float*)d_in[2],  (const float*)d_in[8],  (const float*)d_in[14]};
    const float* linb[3] = {(const float*)d_in[3],  (const float*)d_in[9],  (const float*)d_in[15]};
    const float* att[3]  = {(const float*)d_in[4],  (const float*)d_in[10], (const float*)d_in[16]};
    const float* bias[3] = {(const float*)d_in[5],  (const float*)d_in[11], (const float*)d_in[17]};
    const float* sW[3]   = {(const float*)d_in[6],  (const float*)d_in[12], (const float*)d_in[18]};
    const float* sb[3]   = {(const float*)d_in[7],  (const float*)d_in[13], (const float*)d_in[19]};

    int node_blocks = (NNODES + 255) / 256;
    int edge_blocks = (NEDGES + 255) / 256;

    // decode edges + build CSR (shared by all 3 layers)
    detect_kernel<<<1, 256>>>((const unsigned int*)ei);
    decode_kernel<<<(2 * NEDGES + 255) / 256, 256>>>(ei);
    zero_deg_kernel<<<node_blocks, 256>>>();
    hist_kernel<<<edge_blocks, 256>>>();
    scan1_kernel<<<SCAN_BLOCKS, 256>>>();
    scan2_kernel<<<1, 256>>>();
    scan3_kernel<<<node_blocks, 256>>>();
    copyptr_kernel<<<node_blocks, 256>>>();
    scatter_kernel<<<edge_blocks, 256>>>();

    const int M = NNODES;
    dim3 gemm_grid128(2, (M + BM - 1) / BM);
    dim3 gemm_grid32(1, (M + BM - 1) / BM);
    int attn_blocks = (NNODES + 7) / 8;   // 8 warps (nodes) per block

    for (int l = 0; l < 3; l++) {
        int useGX = (l > 0) ? 1 : 0;
        int skipN = (l < 2) ? 128 : 32;

        gemm_kernel<<<gemm_grid128, 256>>>(x, useGX, W[l], linb[l], M, 128, 0);
        gemm_kernel<<<(skipN == 128 ? gemm_grid128 : gemm_grid32), 256>>>(
            x, useGX, sW[l], sb[l], M, skipN, 1);

        attn_kernel<<<attn_blocks, 256>>>(att[l], bias[l], (l == 2) ? 1 : 0,
                                          (float*)d_out);
    }
}

// round 3
// speedup vs baseline: 2.1915x; 1.1237x over previous
#include <cuda_runtime.h>
#include <cstdint>

#define NNODES 50000
#define NEDGES 600000
#define HC 128
#define NH 4
#define CDIM 32
#define SCAN_BLOCKS ((NNODES + 255) / 256)   // 196

// ---------------- scratch (device globals; no allocation allowed) ----------------
__device__ float g_x[NNODES * HC];
__device__ float g_h[NNODES * HC];
__device__ float g_skip[NNODES * HC];
__device__ int   g_src[NEDGES];
__device__ int   g_dst[NEDGES];
__device__ int   g_deg[NNODES];
__device__ int   g_rowptr[NNODES + 1];
__device__ int   g_ptr[NNODES];
__device__ int   g_bsum[SCAN_BLOCKS];
__device__ int   g_csr_src[NEDGES];
__device__ int   g_is64;

// ---------------- edge_index dtype detection + decode ----------------
__global__ void detect_kernel(const unsigned int* __restrict__ buf) {
    __shared__ int nz;
    if (threadIdx.x == 0) nz = 0;
    __syncthreads();
    if (buf[2 * threadIdx.x + 1] != 0u) atomicOr(&nz, 1);
    __syncthreads();
    if (threadIdx.x == 0) g_is64 = (nz == 0) ? 1 : 0;
}

__global__ void decode_kernel(const void* __restrict__ buf) {
    int i = blockIdx.x * blockDim.x + threadIdx.x;
    if (i >= 2 * NEDGES) return;
    int v;
    if (g_is64) v = (int)(((const long long*)buf)[i]);
    else        v = ((const int*)buf)[i];
    if (i < NEDGES) g_src[i] = v;
    else            g_dst[i - NEDGES] = v;
}

// ---------------- CSR build ----------------
__global__ void zero_deg_kernel() {
    int i = blockIdx.x * blockDim.x + threadIdx.x;
    if (i < NNODES) g_deg[i] = 0;
}

__global__ void hist_kernel() {
    int e = blockIdx.x * blockDim.x + threadIdx.x;
    if (e < NEDGES) atomicAdd(&g_deg[g_dst[e]], 1);
}

__global__ void scan1_kernel() {
    __shared__ int sh[256];
    int i = blockIdx.x * 256 + threadIdx.x;
    int v = (i < NNODES) ? g_deg[i] : 0;
    sh[threadIdx.x] = v;
    __syncthreads();
#pragma unroll
    for (int off = 1; off < 256; off <<= 1) {
        int t = (threadIdx.x >= off) ? sh[threadIdx.x - off] : 0;
        __syncthreads();
        sh[threadIdx.x] += t;
        __syncthreads();
    }
    if (i < NNODES) g_rowptr[i + 1] = sh[threadIdx.x];
    if (threadIdx.x == 255) g_bsum[blockIdx.x] = sh[255];
}

__global__ void scan2_kernel() {
    __shared__ int sh[256];
    int v = (threadIdx.x < SCAN_BLOCKS) ? g_bsum[threadIdx.x] : 0;
    sh[threadIdx.x] = v;
    __syncthreads();
#pragma unroll
    for (int off = 1; off < 256; off <<= 1) {
        int t = (threadIdx.x >= off) ? sh[threadIdx.x - off] : 0;
        __syncthreads();
        sh[threadIdx.x] += t;
        __syncthreads();
    }
    if (threadIdx.x < SCAN_BLOCKS)
        g_bsum[threadIdx.x] = (threadIdx.x == 0) ? 0 : sh[threadIdx.x - 1];
}

__global__ void scan3_kernel() {
    int i = blockIdx.x * blockDim.x + threadIdx.x;
    if (i == 0) g_rowptr[0] = 0;
    if (i < NNODES) g_rowptr[i + 1] += g_bsum[i >> 8];
}

__global__ void copyptr_kernel() {
    int i = blockIdx.x * blockDim.x + threadIdx.x;
    if (i < NNODES) g_ptr[i] = g_rowptr[i];
}

__global__ void scatter_kernel() {
    int e = blockIdx.x * blockDim.x + threadIdx.x;
    if (e >= NEDGES) return;
    int d = g_dst[e];
    int pos = atomicAdd(&g_ptr[d], 1);
    g_csr_src[pos] = g_src[e];
}

// ---------------- tensor-core GEMM (split-tf32, fp32-exact) ----------------
// C[M x NN] = A[M x 128] @ B[128 x NN] + bias, NN in {128, 32}.
// Block: 128 rows x NN cols. A chunk + full B panel resident in dynamic smem.

__device__ __forceinline__ unsigned f2tf(float f) {
    unsigned r;
    asm("cvt.rna.tf32.f32 %0, %1;" : "=r"(r) : "f"(f));
    return r;
}
__device__ __forceinline__ void split_tf(float f, unsigned& hi, unsigned& lo) {
    hi = f2tf(f);
    lo = f2tf(f - __uint_as_float(hi));
}
__device__ __forceinline__ void mma_tf32(float* c, const unsigned* a, const unsigned* b) {
    asm volatile(
        "mma.sync.aligned.m16n8k8.row.col.f32.tf32.tf32.f32 "
        "{%0,%1,%2,%3}, {%4,%5,%6,%7}, {%8,%9}, {%0,%1,%2,%3};"
        : "+f"(c[0]), "+f"(c[1]), "+f"(c[2]), "+f"(c[3])
        : "r"(a[0]), "r"(a[1]), "r"(a[2]), "r"(a[3]), "r"(b[0]), "r"(b[1]));
}

template <int NN>
__global__ __launch_bounds__(256) void gemm_tc(
    const float* __restrict__ A_ext, int useGX,
    const float* __restrict__ B, const float* __restrict__ bias,
    int M, int target /* 0 -> g_h, 1 -> g_skip */) {

    constexpr int WARPS_N = (NN == 128) ? 4 : 1;
    constexpr int WARPS_M = 8 / WARPS_N;     // 2 or 8
    constexpr int WTM = 128 / WARPS_M;       // 64 or 16
    constexpr int MT = WTM / 16;             // 4 or 1
    constexpr int NT = 4;                    // 32 cols / 8
    constexpr int AP = 132;                  // A smem pitch (floats)
    constexpr int BP = NN + 4;               // B smem pitch

    extern __shared__ float sm[];
    float* sA = sm;                 // 128 x AP
    float* sB = sm + 128 * AP;      // 128 x BP

    const float* A = useGX ? g_x : A_ext;
    float* C = target ? g_skip : g_h;

    int tid = threadIdx.x;
    int m0 = blockIdx.x * 128;

    // load A chunk (128 x 128)
#pragma unroll
    for (int i = tid; i < 128 * 32; i += 256) {
        int r = i >> 5, c4 = (i & 31) << 2;
        float4 v = make_float4(0.f, 0.f, 0.f, 0.f);
        if (m0 + r < M) v = *(const float4*)(A + (size_t)(m0 + r) * 128 + c4);
        *(float4*)(sA + r * AP + c4) = v;
    }
    // load B panel (128 x NN)
#pragma unroll
    for (int i = tid; i < 128 * (NN / 4); i += 256) {
        int r = i / (NN / 4), c4 = (i % (NN / 4)) << 2;
        float4 v = *(const float4*)(B + (size_t)r * NN + c4);
        *(float4*)(sB + r * BP + c4) = v;
    }
    __syncthreads();

    int warp = tid >> 5, lane = tid & 31;
    int wm = warp % WARPS_M, wn = warp / WARPS_M;
    int mbase = wm * WTM;
    int nbase = wn * 32;
    int qr = lane >> 2, qc = lane & 3;

    float acc[MT][NT][4];
#pragma unroll
    for (int i = 0; i < MT; i++)
#pragma unroll
        for (int j = 0; j < NT; j++)
#pragma unroll
            for (int q = 0; q < 4; q++) acc[i][j][q] = 0.f;

#pragma unroll
    for (int ks = 0; ks < 16; ks++) {
        int k0 = ks * 8;

        unsigned ah[MT][4], al[MT][4];
#pragma unroll
        for (int mt = 0; mt < MT; mt++) {
            int r = mbase + mt * 16 + qr;
            float a0 = sA[r * AP + k0 + qc];
            float a1 = sA[(r + 8) * AP + k0 + qc];
            float a2 = sA[r * AP + k0 + 4 + qc];
            float a3 = sA[(r + 8) * AP + k0 + 4 + qc];
            split_tf(a0, ah[mt][0], al[mt][0]);
            split_tf(a1, ah[mt][1], al[mt][1]);
            split_tf(a2, ah[mt][2], al[mt][2]);
            split_tf(a3, ah[mt][3], al[mt][3]);
        }
        unsigned bh[NT][2], bl[NT][2];
#pragma unroll
        for (int nt = 0; nt < NT; nt++) {
            int col = nbase + nt * 8 + qr;
            float b0 = sB[(k0 + qc) * BP + col];
            float b1 = sB[(k0 + 4 + qc) * BP + col];
            split_tf(b0, bh[nt][0], bl[nt][0]);
            split_tf(b1, bh[nt][1], bl[nt][1]);
        }
#pragma unroll
        for (int mt = 0; mt < MT; mt++)
#pragma unroll
            for (int nt = 0; nt < NT; nt++) {
                mma_tf32(acc[mt][nt], ah[mt], bh[nt]);
                mma_tf32(acc[mt][nt], al[mt], bh[nt]);
                mma_tf32(acc[mt][nt], ah[mt], bl[nt]);
            }
    }

    // epilogue: C = acc + bias
#pragma unroll
    for (int mt = 0; mt < MT; mt++) {
#pragma unroll
        for (int nt = 0; nt < NT; nt++) {
            int col = nbase + nt * 8 + 2 * qc;
            float bx = __ldg(bias + col), by = __ldg(bias + col + 1);
            int r0 = m0 + mbase + mt * 16 + qr;
            if (r0 < M) {
                float2 o = make_float2(acc[mt][nt][0] + bx, acc[mt][nt][1] + by);
                *(float2*)(C + (size_t)r0 * NN + col) = o;
            }
            if (r0 + 8 < M) {
                float2 o = make_float2(acc[mt][nt][2] + bx, acc[mt][nt][3] + by);
                *(float2*)(C + (size_t)(r0 + 8) * NN + col) = o;
            }
        }
    }
}

// ---------------- fused attention: online softmax, warp per dst node ----------------
__device__ __forceinline__ float lrelu(float v) {
    return fmaxf(v, 0.f) + 0.2f * fminf(v, 0.f);
}

__global__ __launch_bounds__(256) void attn_kernel(
    const float* __restrict__ att, const float* __restrict__ bias,
    int last, float* __restrict__ out) {

    int gw = (blockIdx.x * blockDim.x + threadIdx.x) >> 5;
    int lane = threadIdx.x & 31;
    if (gw >= NNODES) return;
    int n = gw;

    float4 att4 = ((const float4*)att)[lane];
    float4 hd4  = ((const float4*)(g_h + (size_t)n * HC))[lane];

    float m = __int_as_float(0xff800000);
    float denom = 0.f;
    float4 acc = make_float4(0.f, 0.f, 0.f, 0.f);

    int start = g_rowptr[n];
    int end   = g_rowptr[n + 1];

    for (int base = start; base < end; base += 32) {
        int cnt = min(32, end - base);
        int sidx = (lane < cnt) ? g_csr_src[base + lane] : 0;
        for (int e = 0; e < cnt; e++) {
            int s = __shfl_sync(0xffffffffu, sidx, e);
            float4 hs4 = *((const float4*)(g_h + (size_t)s * HC) + lane);

            float part = lrelu(hs4.x + hd4.x) * att4.x
                       + lrelu(hs4.y + hd4.y) * att4.y
                       + lrelu(hs4.z + hd4.z) * att4.z
                       + lrelu(hs4.w + hd4.w) * att4.w;
            part += __shfl_xor_sync(0xffffffffu, part, 1);
            part += __shfl_xor_sync(0xffffffffu, part, 2);
            part += __shfl_xor_sync(0xffffffffu, part, 4);

            float mn = fmaxf(m, part);
            float scale = __expf(m - mn);
            float p = __expf(part - mn);
            denom = denom * scale + p;
            acc.x = acc.x * scale + p * hs4.x;
            acc.y = acc.y * scale + p * hs4.y;
            acc.z = acc.z * scale + p * hs4.z;
            acc.w = acc.w * scale + p * hs4.w;
            m = mn;
        }
    }

    float inv = 1.0f / fmaxf(denom, 1e-16f);

    if (!last) {
        float4 sk = ((const float4*)(g_skip + (size_t)n * HC))[lane];
        float4 b4 = ((const float4*)bias)[lane];
        float4 o;
        o.x = acc.x * inv + b4.x + sk.x;
        o.y = acc.y * inv + b4.y + sk.y;
        o.z = acc.z * inv + b4.z + sk.z;
        o.w = acc.w * inv + b4.w + sk.w;
        o.x = o.x > 0.f ? o.x : expm1f(o.x);
        o.y = o.y > 0.f ? o.y : expm1f(o.y);
        o.z = o.z > 0.f ? o.z : expm1f(o.z);
        o.w = o.w > 0.f ? o.w : expm1f(o.w);
        ((float4*)(g_x + (size_t)n * HC))[lane] = o;
    } else {
        float4 r;
        r.x = acc.x * inv; r.y = acc.y * inv; r.z = acc.z * inv; r.w = acc.w * inv;
        r.x += __shfl_xor_sync(0xffffffffu, r.x, 8);
        r.y += __shfl_xor_sync(0xffffffffu, r.y, 8);
        r.z += __shfl_xor_sync(0xffffffffu, r.z, 8);
        r.w += __shfl_xor_sync(0xffffffffu, r.w, 8);
        r.x += __shfl_xor_sync(0xffffffffu, r.x, 16);
        r.y += __shfl_xor_sync(0xffffffffu, r.y, 16);
        r.z += __shfl_xor_sync(0xffffffffu, r.z, 16);
        r.w += __shfl_xor_sync(0xffffffffu, r.w, 16);
        if (lane < 8) {
            float4 sk = ((const float4*)(g_skip + (size_t)n * CDIM))[lane];
            float4 b4 = ((const float4*)bias)[lane];
            float4 o;
            o.x = 0.25f * r.x + b4.x + sk.x;
            o.y = 0.25f * r.y + b4.y + sk.y;
            o.z = 0.25f * r.z + b4.z + sk.z;
            o.w = 0.25f * r.w + b4.w + sk.w;
            ((float4*)(out + (size_t)n * CDIM))[lane] = o;
        }
    }
}

// ---------------- launch ----------------
extern "C" void kernel_launch(void* const* d_in, const int* in_sizes, int n_in,
                              void* d_out, int out_size) {
    const float* x  = (const float*)d_in[0];
    const void*  ei = d_in[1];
    const float* W[3]    = {(const float*)d_in[2],  (const float*)d_in[8],  (const float*)d_in[14]};
    const float* linb[3] = {(const float*)d_in[3],  (const float*)d_in[9],  (const float*)d_in[15]};
    const float* att[3]  = {(const float*)d_in[4],  (const float*)d_in[10], (const float*)d_in[16]};
    const float* bias[3] = {(const float*)d_in[5],  (const float*)d_in[11], (const float*)d_in[17]};
    const float* sW[3]   = {(const float*)d_in[6],  (const float*)d_in[12], (const float*)d_in[18]};
    const float* sb[3]   = {(const float*)d_in[7],  (const float*)d_in[13], (const float*)d_in[19]};

    int node_blocks = (NNODES + 255) / 256;
    int edge_blocks = (NEDGES + 255) / 256;

    const int smem128 = (128 * 132 + 128 * 132) * 4;  // 135168
    const int smem32  = (128 * 132 + 128 * 36) * 4;   //  86016
    cudaFuncSetAttribute(gemm_tc<128>, cudaFuncAttributeMaxDynamicSharedMemorySize, smem128);
    cudaFuncSetAttribute(gemm_tc<32>,  cudaFuncAttributeMaxDynamicSharedMemorySize, smem32);

    // decode edges + build CSR (shared by all 3 layers)
    detect_kernel<<<1, 256>>>((const unsigned int*)ei);
    decode_kernel<<<(2 * NEDGES + 255) / 256, 256>>>(ei);
    zero_deg_kernel<<<node_blocks, 256>>>();
    hist_kernel<<<edge_blocks, 256>>>();
    scan1_kernel<<<SCAN_BLOCKS, 256>>>();
    scan2_kernel<<<1, 256>>>();
    scan3_kernel<<<node_blocks, 256>>>();
    copyptr_kernel<<<node_blocks, 256>>>();
    scatter_kernel<<<edge_blocks, 256>>>();

    const int M = NNODES;
    int gemm_blocks = (M + 127) / 128;   // 391
    int attn_blocks = (NNODES + 7) / 8;

    for (int l = 0; l < 3; l++) {
        int useGX = (l > 0) ? 1 : 0;

        gemm_tc<128><<<gemm_blocks, 256, smem128>>>(x, useGX, W[l], linb[l], M, 0);
        if (l < 2)
            gemm_tc<128><<<gemm_blocks, 256, smem128>>>(x, useGX, sW[l], sb[l], M, 1);
        else
            gemm_tc<32><<<gemm_blocks, 256, smem32>>>(x, useGX, sW[l], sb[l], M, 1);

        attn_kernel<<<attn_blocks, 256>>>(att[l], bias[l], (l == 2) ? 1 : 0,
                                          (float*)d_out);
    }
}

// round 4
// speedup vs baseline: 2.6068x; 1.1895x over previous
#include <cuda_runtime.h>
#include <cuda_bf16.h>
#include <cstdint>

#define NNODES 50000
#define NEDGES 600000
#define HC 128
#define NH 4
#define CDIM 32
#define SCAN_BLOCKS ((NNODES + 255) / 256)   // 196

// ---------------- scratch (device globals; no allocation allowed) ----------------
__device__ float g_x[NNODES * HC];
__device__ float g_h[NNODES * HC];
__device__ float g_skip[NNODES * HC];
__device__ int   g_src[NEDGES];
__device__ int   g_dst[NEDGES];
__device__ int   g_deg[NNODES];
__device__ int   g_rowptr[NNODES + 1];
__device__ int   g_ptr[NNODES];
__device__ int   g_bsum[SCAN_BLOCKS];
__device__ int   g_csr_src[NEDGES];
__device__ int   g_is64;

// ---------------- edge_index dtype detection + decode ----------------
__global__ void detect_kernel(const unsigned int* __restrict__ buf) {
    __shared__ int nz;
    if (threadIdx.x == 0) nz = 0;
    __syncthreads();
    if (buf[2 * threadIdx.x + 1] != 0u) atomicOr(&nz, 1);
    __syncthreads();
    if (threadIdx.x == 0) g_is64 = (nz == 0) ? 1 : 0;
}

__global__ void decode_kernel(const void* __restrict__ buf) {
    int i = blockIdx.x * blockDim.x + threadIdx.x;
    if (i >= 2 * NEDGES) return;
    int v;
    if (g_is64) v = (int)(((const long long*)buf)[i]);
    else        v = ((const int*)buf)[i];
    if (i < NEDGES) g_src[i] = v;
    else            g_dst[i - NEDGES] = v;
}

// ---------------- CSR build ----------------
__global__ void zero_deg_kernel() {
    int i = blockIdx.x * blockDim.x + threadIdx.x;
    if (i < NNODES) g_deg[i] = 0;
}

__global__ void hist_kernel() {
    int e = blockIdx.x * blockDim.x + threadIdx.x;
    if (e < NEDGES) atomicAdd(&g_deg[g_dst[e]], 1);
}

__global__ void scan1_kernel() {
    __shared__ int sh[256];
    int i = blockIdx.x * 256 + threadIdx.x;
    int v = (i < NNODES) ? g_deg[i] : 0;
    sh[threadIdx.x] = v;
    __syncthreads();
#pragma unroll
    for (int off = 1; off < 256; off <<= 1) {
        int t = (threadIdx.x >= off) ? sh[threadIdx.x - off] : 0;
        __syncthreads();
        sh[threadIdx.x] += t;
        __syncthreads();
    }
    if (i < NNODES) g_rowptr[i + 1] = sh[threadIdx.x];
    if (threadIdx.x == 255) g_bsum[blockIdx.x] = sh[255];
}

__global__ void scan2_kernel() {
    __shared__ int sh[256];
    int v = (threadIdx.x < SCAN_BLOCKS) ? g_bsum[threadIdx.x] : 0;
    sh[threadIdx.x] = v;
    __syncthreads();
#pragma unroll
    for (int off = 1; off < 256; off <<= 1) {
        int t = (threadIdx.x >= off) ? sh[threadIdx.x - off] : 0;
        __syncthreads();
        sh[threadIdx.x] += t;
        __syncthreads();
    }
    if (threadIdx.x < SCAN_BLOCKS)
        g_bsum[threadIdx.x] = (threadIdx.x == 0) ? 0 : sh[threadIdx.x - 1];
}

__global__ void scan3_kernel() {
    int i = blockIdx.x * blockDim.x + threadIdx.x;
    if (i == 0) g_rowptr[0] = 0;
    if (i < NNODES) g_rowptr[i + 1] += g_bsum[i >> 8];
}

__global__ void copyptr_kernel() {
    int i = blockIdx.x * blockDim.x + threadIdx.x;
    if (i < NNODES) g_ptr[i] = g_rowptr[i];
}

__global__ void scatter_kernel() {
    int e = blockIdx.x * blockDim.x + threadIdx.x;
    if (e >= NEDGES) return;
    int d = g_dst[e];
    int pos = atomicAdd(&g_ptr[d], 1);
    g_csr_src[pos] = g_src[e];
}

// ---------------- tensor-core GEMM (split-bf16, ~fp32 accuracy) ----------------
// C[M x NN] = A[M x 128] @ B[128 x NN] + bias, NN in {128, 32}.
// hi/lo bf16 splits precomputed in smem; fragments via ldmatrix; 3-term MMA.

__device__ __forceinline__ unsigned pack_hi(float a, float b) {
    unsigned short ha = __bfloat16_as_ushort(__float2bfloat16(a));
    unsigned short hb = __bfloat16_as_ushort(__float2bfloat16(b));
    return (unsigned)ha | ((unsigned)hb << 16);
}
__device__ __forceinline__ unsigned pack_lo(float a, float b) {
    float ra = a - __bfloat162float(__float2bfloat16(a));
    float rb = b - __bfloat162float(__float2bfloat16(b));
    unsigned short la = __bfloat16_as_ushort(__float2bfloat16(ra));
    unsigned short lb = __bfloat16_as_ushort(__float2bfloat16(rb));
    return (unsigned)la | ((unsigned)lb << 16);
}

__device__ __forceinline__ void ldmx4(unsigned* r, unsigned addr) {
    asm volatile("ldmatrix.sync.aligned.m8n8.x4.shared.b16 {%0,%1,%2,%3}, [%4];"
                 : "=r"(r[0]), "=r"(r[1]), "=r"(r[2]), "=r"(r[3]) : "r"(addr));
}
__device__ __forceinline__ void ldmx4t(unsigned* r, unsigned addr) {
    asm volatile("ldmatrix.sync.aligned.m8n8.x4.trans.shared.b16 {%0,%1,%2,%3}, [%4];"
                 : "=r"(r[0]), "=r"(r[1]), "=r"(r[2]), "=r"(r[3]) : "r"(addr));
}
__device__ __forceinline__ void mma_bf16(float* c, const unsigned* a, const unsigned* b) {
    asm volatile(
        "mma.sync.aligned.m16n8k16.row.col.f32.bf16.bf16.f32 "
        "{%0,%1,%2,%3}, {%4,%5,%6,%7}, {%8,%9}, {%0,%1,%2,%3};"
        : "+f"(c[0]), "+f"(c[1]), "+f"(c[2]), "+f"(c[3])
        : "r"(a[0]), "r"(a[1]), "r"(a[2]), "r"(a[3]), "r"(b[0]), "r"(b[1]));
}

template <int NN>
__global__ __launch_bounds__(256) void gemm_bf(
    const float* __restrict__ A_ext, int useGX,
    const float* __restrict__ B, const float* __restrict__ bias,
    int M, int target /* 0 -> g_h, 1 -> g_skip */) {

    constexpr int WARPS_N = (NN == 128) ? 4 : 1;
    constexpr int WARPS_M = 8 / WARPS_N;     // 2 or 8
    constexpr int WTM = 128 / WARPS_M;       // 64 or 16
    constexpr int MT = WTM / 16;             // 4 or 1
    constexpr int NT = 4;                    // 32 cols / 8
    constexpr int AP = 136;                  // A smem pitch (bf16 elems)
    constexpr int BP = (NN == 128) ? 136 : 40;

    extern __shared__ char smch[];
    unsigned* sAh32 = (unsigned*)smch;                         // 128*AP bf16 = 128*68 u32
    unsigned* sAl32 = sAh32 + 128 * (AP / 2);
    unsigned* sBh32 = sAl32 + 128 * (AP / 2);
    unsigned* sBl32 = sBh32 + 128 * (BP / 2);

    const float* A = useGX ? g_x : A_ext;
    float* C = target ? g_skip : g_h;

    int tid = threadIdx.x;
    int m0 = blockIdx.x * 128;

    // load + split A chunk (128 x 128)
#pragma unroll
    for (int it = 0; it < 16; it++) {
        int i = tid + it * 256;
        int r = i >> 5, c4 = (i & 31) << 2;
        float4 v = make_float4(0.f, 0.f, 0.f, 0.f);
        if (m0 + r < M) v = *(const float4*)(A + (size_t)(m0 + r) * 128 + c4);
        int w = r * (AP / 2) + (c4 >> 1);
        sAh32[w]     = pack_hi(v.x, v.y);
        sAh32[w + 1] = pack_hi(v.z, v.w);
        sAl32[w]     = pack_lo(v.x, v.y);
        sAl32[w + 1] = pack_lo(v.z, v.w);
    }
    // load + split B panel (128 x NN), k-major
#pragma unroll
    for (int it = 0; it < 128 * (NN / 4) / 256; it++) {
        int i = tid + it * 256;
        int k = i / (NN / 4), n4 = (i % (NN / 4)) << 2;
        float4 v = *(const float4*)(B + (size_t)k * NN + n4);
        int w = k * (BP / 2) + (n4 >> 1);
        sBh32[w]     = pack_hi(v.x, v.y);
        sBh32[w + 1] = pack_hi(v.z, v.w);
        sBl32[w]     = pack_lo(v.x, v.y);
        sBl32[w + 1] = pack_lo(v.z, v.w);
    }
    __syncthreads();

    int warp = tid >> 5, lane = tid & 31;
    int wm = warp % WARPS_M, wn = warp / WARPS_M;
    int mbase = wm * WTM;
    int nbase = wn * 32;
    int qr = lane >> 2, qc = lane & 3;

    unsigned sAh_s = (unsigned)__cvta_generic_to_shared(sAh32);
    unsigned sAl_s = (unsigned)__cvta_generic_to_shared(sAl32);
    unsigned sBh_s = (unsigned)__cvta_generic_to_shared(sBh32);
    unsigned sBl_s = (unsigned)__cvta_generic_to_shared(sBl32);

    // per-lane ldmatrix base offsets (bytes)
    int aRow = mbase + (lane & 15);
    int aKof = (lane >> 4) << 3;
    unsigned aOff = (unsigned)((aRow * AP + aKof) * 2);
    int bK   = lane & 15;
    int bNof = nbase + ((lane >> 4) << 3);
    unsigned bOff = (unsigned)((bK * BP + bNof) * 2);

    float acc[MT][NT][4];
#pragma unroll
    for (int i = 0; i < MT; i++)
#pragma unroll
        for (int j = 0; j < NT; j++)
#pragma unroll
            for (int q = 0; q < 4; q++) acc[i][j][q] = 0.f;

#pragma unroll
    for (int ks = 0; ks < 8; ks++) {
        int k0 = ks * 16;

        unsigned ah[MT][4], al[MT][4];
#pragma unroll
        for (int mt = 0; mt < MT; mt++) {
            unsigned off = aOff + (unsigned)((mt * 16 * AP + k0) * 2);
            ldmx4(ah[mt], sAh_s + off);
            ldmx4(al[mt], sAl_s + off);
        }
        unsigned bh[NT][2], bl[NT][2];
#pragma unroll
        for (int np = 0; np < NT / 2; np++) {
            unsigned off = bOff + (unsigned)((k0 * BP + np * 16) * 2);
            unsigned t[4];
            ldmx4t(t, sBh_s + off);
            bh[2 * np][0] = t[0]; bh[2 * np][1] = t[1];
            bh[2 * np + 1][0] = t[2]; bh[2 * np + 1][1] = t[3];
            ldmx4t(t, sBl_s + off);
            bl[2 * np][0] = t[0]; bl[2 * np][1] = t[1];
            bl[2 * np + 1][0] = t[2]; bl[2 * np + 1][1] = t[3];
        }
#pragma unroll
        for (int mt = 0; mt < MT; mt++)
#pragma unroll
            for (int nt = 0; nt < NT; nt++) {
                mma_bf16(acc[mt][nt], ah[mt], bh[nt]);
                mma_bf16(acc[mt][nt], al[mt], bh[nt]);
                mma_bf16(acc[mt][nt], ah[mt], bl[nt]);
            }
    }

    // epilogue: C = acc + bias
#pragma unroll
    for (int mt = 0; mt < MT; mt++) {
#pragma unroll
        for (int nt = 0; nt < NT; nt++) {
            int col = nbase + nt * 8 + 2 * qc;
            float bx = __ldg(bias + col), by = __ldg(bias + col + 1);
            int r0 = m0 + mbase + mt * 16 + qr;
            if (r0 < M) {
                float2 o = make_float2(acc[mt][nt][0] + bx, acc[mt][nt][1] + by);
                *(float2*)(C + (size_t)r0 * NN + col) = o;
            }
            if (r0 + 8 < M) {
                float2 o = make_float2(acc[mt][nt][2] + bx, acc[mt][nt][3] + by);
                *(float2*)(C + (size_t)(r0 + 8) * NN + col) = o;
            }
        }
    }
}

// ---------------- fused attention: online softmax, warp per dst node ----------------
__device__ __forceinline__ float lrelu(float v) {
    return fmaxf(v, 0.f) + 0.2f * fminf(v, 0.f);
}

__global__ __launch_bounds__(256) void attn_kernel(
    const float* __restrict__ att, const float* __restrict__ bias,
    int last, float* __restrict__ out) {

    int gw = (blockIdx.x * blockDim.x + threadIdx.x) >> 5;
    int lane = threadIdx.x & 31;
    if (gw >= NNODES) return;
    int n = gw;

    float4 att4 = ((const float4*)att)[lane];
    float4 hd4  = ((const float4*)(g_h + (size_t)n * HC))[lane];

    float m = __int_as_float(0xff800000);
    float denom = 0.f;
    float4 acc = make_float4(0.f, 0.f, 0.f, 0.f);

    int start = g_rowptr[n];
    int end   = g_rowptr[n + 1];

    for (int base = start; base < end; base += 32) {
        int cnt = min(32, end - base);
        int sidx = (lane < cnt) ? g_csr_src[base + lane] : 0;
        for (int e = 0; e < cnt; e++) {
            int s = __shfl_sync(0xffffffffu, sidx, e);
            float4 hs4 = *((const float4*)(g_h + (size_t)s * HC) + lane);

            float part = lrelu(hs4.x + hd4.x) * att4.x
                       + lrelu(hs4.y + hd4.y) * att4.y
                       + lrelu(hs4.z + hd4.z) * att4.z
                       + lrelu(hs4.w + hd4.w) * att4.w;
            part += __shfl_xor_sync(0xffffffffu, part, 1);
            part += __shfl_xor_sync(0xffffffffu, part, 2);
            part += __shfl_xor_sync(0xffffffffu, part, 4);

            float mn = fmaxf(m, part);
            float scale = __expf(m - mn);
            float p = __expf(part - mn);
            denom = denom * scale + p;
            acc.x = acc.x * scale + p * hs4.x;
            acc.y = acc.y * scale + p * hs4.y;
            acc.z = acc.z * scale + p * hs4.z;
            acc.w = acc.w * scale + p * hs4.w;
            m = mn;
        }
    }

    float inv = 1.0f / fmaxf(denom, 1e-16f);

    if (!last) {
        float4 sk = ((const float4*)(g_skip + (size_t)n * HC))[lane];
        float4 b4 = ((const float4*)bias)[lane];
        float4 o;
        o.x = acc.x * inv + b4.x + sk.x;
        o.y = acc.y * inv + b4.y + sk.y;
        o.z = acc.z * inv + b4.z + sk.z;
        o.w = acc.w * inv + b4.w + sk.w;
        o.x = o.x > 0.f ? o.x : expm1f(o.x);
        o.y = o.y > 0.f ? o.y : expm1f(o.y);
        o.z = o.z > 0.f ? o.z : expm1f(o.z);
        o.w = o.w > 0.f ? o.w : expm1f(o.w);
        ((float4*)(g_x + (size_t)n * HC))[lane] = o;
    } else {
        float4 r;
        r.x = acc.x * inv; r.y = acc.y * inv; r.z = acc.z * inv; r.w = acc.w * inv;
        r.x += __shfl_xor_sync(0xffffffffu, r.x, 8);
        r.y += __shfl_xor_sync(0xffffffffu, r.y, 8);
        r.z += __shfl_xor_sync(0xffffffffu, r.z, 8);
        r.w += __shfl_xor_sync(0xffffffffu, r.w, 8);
        r.x += __shfl_xor_sync(0xffffffffu, r.x, 16);
        r.y += __shfl_xor_sync(0xffffffffu, r.y, 16);
        r.z += __shfl_xor_sync(0xffffffffu, r.z, 16);
        r.w += __shfl_xor_sync(0xffffffffu, r.w, 16);
        if (lane < 8) {
            float4 sk = ((const float4*)(g_skip + (size_t)n * CDIM))[lane];
            float4 b4 = ((const float4*)bias)[lane];
            float4 o;
            o.x = 0.25f * r.x + b4.x + sk.x;
            o.y = 0.25f * r.y + b4.y + sk.y;
            o.z = 0.25f * r.z + b4.z + sk.z;
            o.w = 0.25f * r.w + b4.w + sk.w;
            ((float4*)(out + (size_t)n * CDIM))[lane] = o;
        }
    }
}

// ---------------- launch ----------------
extern "C" void kernel_launch(void* const* d_in, const int* in_sizes, int n_in,
                              void* d_out, int out_size) {
    const float* x  = (const float*)d_in[0];
    const void*  ei = d_in[1];
    const float* W[3]    = {(const float*)d_in[2],  (const float*)d_in[8],  (const float*)d_in[14]};
    const float* linb[3] = {(const float*)d_in[3],  (const float*)d_in[9],  (const float*)d_in[15]};
    const float* att[3]  = {(const float*)d_in[4],  (const float*)d_in[10], (const float*)d_in[16]};
    const float* bias[3] = {(const float*)d_in[5],  (const float*)d_in[11], (const float*)d_in[17]};
    const float* sW[3]   = {(const float*)d_in[6],  (const float*)d_in[12], (const float*)d_in[18]};
    const float* sb[3]   = {(const float*)d_in[7],  (const float*)d_in[13], (const float*)d_in[19]};

    int node_blocks = (NNODES + 255) / 256;
    int edge_blocks = (NEDGES + 255) / 256;

    const int smem128 = (128 * 136 + 128 * 136) * 2 * 2;  // A(hi,lo)+B(hi,lo) = 139264
    const int smem32  = (128 * 136 + 128 * 40) * 2 * 2;   // 90112
    cudaFuncSetAttribute(gemm_bf<128>, cudaFuncAttributeMaxDynamicSharedMemorySize, smem128);
    cudaFuncSetAttribute(gemm_bf<32>,  cudaFuncAttributeMaxDynamicSharedMemorySize, smem32);

    // decode edges + build CSR (shared by all 3 layers)
    detect_kernel<<<1, 256>>>((const unsigned int*)ei);
    decode_kernel<<<(2 * NEDGES + 255) / 256, 256>>>(ei);
    zero_deg_kernel<<<node_blocks, 256>>>();
    hist_kernel<<<edge_blocks, 256>>>();
    scan1_kernel<<<SCAN_BLOCKS, 256>>>();
    scan2_kernel<<<1, 256>>>();
    scan3_kernel<<<node_blocks, 256>>>();
    copyptr_kernel<<<node_blocks, 256>>>();
    scatter_kernel<<<edge_blocks, 256>>>();

    const int M = NNODES;
    int gemm_blocks = (M + 127) / 128;   // 391
    int attn_blocks = (NNODES + 7) / 8;

    for (int l = 0; l < 3; l++) {
        int useGX = (l > 0) ? 1 : 0;

        gemm_bf<128><<<gemm_blocks, 256, smem128>>>(x, useGX, W[l], linb[l], M, 0);
        if (l < 2)
            gemm_bf<128><<<gemm_blocks, 256, smem128>>>(x, useGX, sW[l], sb[l], M, 1);
        else
            gemm_bf<32><<<gemm_blocks, 256, smem32>>>(x, useGX, sW[l], sb[l], M, 1);

        attn_kernel<<<attn_blocks, 256>>>(att[l], bias[l], (l == 2) ? 1 : 0,
                                          (float*)d_out);
    }
}

// round 5
// speedup vs baseline: 3.1133x; 1.1943x over previous
#include <cuda_runtime.h>
#include <cuda_bf16.h>
#include <cstdint>

#define NNODES 50000
#define NEDGES 600000
#define HC 128
#define NH 4
#define CDIM 32
#define SCAN_BLOCKS ((NNODES + 255) / 256)   // 196

// ---------------- scratch (device globals; no allocation allowed) ----------------
__device__ float g_x[NNODES * HC];
__device__ float g_h[NNODES * HC];
__device__ float g_skip[NNODES * HC];
__device__ int   g_src[NEDGES];
__device__ int   g_dst[NEDGES];
__device__ int   g_deg[NNODES];
__device__ int   g_rowptr[NNODES + 1];
__device__ int   g_ptr[NNODES];
__device__ int   g_bsum[SCAN_BLOCKS];
__device__ int   g_csr_src[NEDGES];
__device__ int   g_is64;

// ---------------- edge_index dtype detection ----------------
__global__ void detect_kernel(const unsigned int* __restrict__ buf) {
    __shared__ int nz;
    if (threadIdx.x == 0) nz = 0;
    __syncthreads();
    if (buf[2 * threadIdx.x + 1] != 0u) atomicOr(&nz, 1);
    __syncthreads();
    if (threadIdx.x == 0) g_is64 = (nz == 0) ? 1 : 0;
}

__global__ void zero_deg_kernel() {
    int i = blockIdx.x * blockDim.x + threadIdx.x;
    if (i < NNODES) g_deg[i] = 0;
}

// decode edge_index AND histogram dst degrees in one pass
__global__ void decode_hist_kernel(const void* __restrict__ buf) {
    int i = blockIdx.x * blockDim.x + threadIdx.x;
    if (i >= 2 * NEDGES) return;
    int v;
    if (g_is64) v = (int)(((const long long*)buf)[i]);
    else        v = ((const int*)buf)[i];
    if (i < NEDGES) g_src[i] = v;
    else {
        g_dst[i - NEDGES] = v;
        atomicAdd(&g_deg[v], 1);
    }
}

// ---------------- CSR scan ----------------
__global__ void scan1_kernel() {
    __shared__ int sh[256];
    int i = blockIdx.x * 256 + threadIdx.x;
    int v = (i < NNODES) ? g_deg[i] : 0;
    sh[threadIdx.x] = v;
    __syncthreads();
#pragma unroll
    for (int off = 1; off < 256; off <<= 1) {
        int t = (threadIdx.x >= off) ? sh[threadIdx.x - off] : 0;
        __syncthreads();
        sh[threadIdx.x] += t;
        __syncthreads();
    }
    if (i < NNODES) g_rowptr[i + 1] = sh[threadIdx.x];
    if (threadIdx.x == 255) g_bsum[blockIdx.x] = sh[255];
}

__global__ void scan2_kernel() {
    __shared__ int sh[256];
    int v = (threadIdx.x < SCAN_BLOCKS) ? g_bsum[threadIdx.x] : 0;
    sh[threadIdx.x] = v;
    __syncthreads();
#pragma unroll
    for (int off = 1; off < 256; off <<= 1) {
        int t = (threadIdx.x >= off) ? sh[threadIdx.x - off] : 0;
        __syncthreads();
        sh[threadIdx.x] += t;
        __syncthreads();
    }
    if (threadIdx.x < SCAN_BLOCKS)
        g_bsum[threadIdx.x] = (threadIdx.x == 0) ? 0 : sh[threadIdx.x - 1];
}

// finalize rowptr and also initialize g_ptr (scatter cursors)
__global__ void scan3_kernel() {
    int i = blockIdx.x * blockDim.x + threadIdx.x;
    if (i == 0) { g_rowptr[0] = 0; g_ptr[0] = 0; }
    if (i < NNODES) {
        int v = g_rowptr[i + 1] + g_bsum[i >> 8];
        g_rowptr[i + 1] = v;
        if (i + 1 < NNODES) g_ptr[i + 1] = v;
    }
}

__global__ void scatter_kernel() {
    int e = blockIdx.x * blockDim.x + threadIdx.x;
    if (e >= NEDGES) return;
    int d = g_dst[e];
    int pos = atomicAdd(&g_ptr[d], 1);
    g_csr_src[pos] = g_src[e];
}

// ---------------- tensor-core GEMM helpers (split-bf16) ----------------
__device__ __forceinline__ unsigned pack_hi(float a, float b) {
    unsigned short ha = __bfloat16_as_ushort(__float2bfloat16(a));
    unsigned short hb = __bfloat16_as_ushort(__float2bfloat16(b));
    return (unsigned)ha | ((unsigned)hb << 16);
}
__device__ __forceinline__ unsigned pack_lo(float a, float b) {
    float ra = a - __bfloat162float(__float2bfloat16(a));
    float rb = b - __bfloat162float(__float2bfloat16(b));
    unsigned short la = __bfloat16_as_ushort(__float2bfloat16(ra));
    unsigned short lb = __bfloat16_as_ushort(__float2bfloat16(rb));
    return (unsigned)la | ((unsigned)lb << 16);
}
__device__ __forceinline__ void ldmx4(unsigned* r, unsigned addr) {
    asm volatile("ldmatrix.sync.aligned.m8n8.x4.shared.b16 {%0,%1,%2,%3}, [%4];"
                 : "=r"(r[0]), "=r"(r[1]), "=r"(r[2]), "=r"(r[3]) : "r"(addr));
}
__device__ __forceinline__ void ldmx4t(unsigned* r, unsigned addr) {
    asm volatile("ldmatrix.sync.aligned.m8n8.x4.trans.shared.b16 {%0,%1,%2,%3}, [%4];"
                 : "=r"(r[0]), "=r"(r[1]), "=r"(r[2]), "=r"(r[3]) : "r"(addr));
}
__device__ __forceinline__ void mma_bf16(float* c, const unsigned* a, const unsigned* b) {
    asm volatile(
        "mma.sync.aligned.m16n8k16.row.col.f32.bf16.bf16.f32 "
        "{%0,%1,%2,%3}, {%4,%5,%6,%7}, {%8,%9}, {%0,%1,%2,%3};"
        : "+f"(c[0]), "+f"(c[1]), "+f"(c[2]), "+f"(c[3])
        : "r"(a[0]), "r"(a[1]), "r"(a[2]), "r"(a[3]), "r"(b[0]), "r"(b[1]));
}

#define AP 136   // A smem pitch (bf16 elems)

template <int NN>
__device__ __forceinline__ void load_split_B(const float* __restrict__ B,
                                             unsigned* sBh, unsigned* sBl, int tid) {
    constexpr int BP = (NN == 128) ? 136 : 40;
#pragma unroll
    for (int it = 0; it < 128 * (NN / 4) / 256; it++) {
        int i = tid + it * 256;
        int k = i / (NN / 4), n4 = (i % (NN / 4)) << 2;
        float4 v = *(const float4*)(B + (size_t)k * NN + n4);
        int w = k * (BP / 2) + (n4 >> 1);
        sBh[w]     = pack_hi(v.x, v.y);
        sBh[w + 1] = pack_hi(v.z, v.w);
        sBl[w]     = pack_lo(v.x, v.y);
        sBl[w + 1] = pack_lo(v.z, v.w);
    }
}

template <int NN>
__device__ __forceinline__ void mma_panel(
    unsigned sAh_s, unsigned sAl_s, unsigned sBh_s, unsigned sBl_s,
    float* __restrict__ C, const float* __restrict__ bias,
    int M, int m0, int warp, int lane) {

    constexpr int WARPS_N = (NN == 128) ? 4 : 1;
    constexpr int WARPS_M = 8 / WARPS_N;     // 2 or 8
    constexpr int WTM = 128 / WARPS_M;       // 64 or 16
    constexpr int MT = WTM / 16;             // 4 or 1
    constexpr int NT = 4;
    constexpr int BP = (NN == 128) ? 136 : 40;

    int wm = warp % WARPS_M, wn = warp / WARPS_M;
    int mbase = wm * WTM;
    int nbase = wn * 32;
    int qr = lane >> 2, qc = lane & 3;

    int aRow = mbase + (lane & 15);
    int aKof = (lane >> 4) << 3;
    unsigned aOff = (unsigned)((aRow * AP + aKof) * 2);
    int bK   = lane & 15;
    int bNof = nbase + ((lane >> 4) << 3);
    unsigned bOff = (unsigned)((bK * BP + bNof) * 2);

    float acc[MT][NT][4];
#pragma unroll
    for (int i = 0; i < MT; i++)
#pragma unroll
        for (int j = 0; j < NT; j++)
#pragma unroll
            for (int q = 0; q < 4; q++) acc[i][j][q] = 0.f;

#pragma unroll
    for (int ks = 0; ks < 8; ks++) {
        int k0 = ks * 16;

        unsigned ah[MT][4], al[MT][4];
#pragma unroll
        for (int mt = 0; mt < MT; mt++) {
            unsigned off = aOff + (unsigned)((mt * 16 * AP + k0) * 2);
            ldmx4(ah[mt], sAh_s + off);
            ldmx4(al[mt], sAl_s + off);
        }
        unsigned bh[NT][2], bl[NT][2];
#pragma unroll
        for (int np = 0; np < NT / 2; np++) {
            unsigned off = bOff + (unsigned)((k0 * BP + np * 16) * 2);
            unsigned t[4];
            ldmx4t(t, sBh_s + off);
            bh[2 * np][0] = t[0]; bh[2 * np][1] = t[1];
            bh[2 * np + 1][0] = t[2]; bh[2 * np + 1][1] = t[3];
            ldmx4t(t, sBl_s + off);
            bl[2 * np][0] = t[0]; bl[2 * np][1] = t[1];
            bl[2 * np + 1][0] = t[2]; bl[2 * np + 1][1] = t[3];
        }
#pragma unroll
        for (int mt = 0; mt < MT; mt++)
#pragma unroll
            for (int nt = 0; nt < NT; nt++) {
                mma_bf16(acc[mt][nt], ah[mt], bh[nt]);
                mma_bf16(acc[mt][nt], al[mt], bh[nt]);
                mma_bf16(acc[mt][nt], ah[mt], bl[nt]);
            }
    }

#pragma unroll
    for (int mt = 0; mt < MT; mt++) {
#pragma unroll
        for (int nt = 0; nt < NT; nt++) {
            int col = nbase + nt * 8 + 2 * qc;
            float bx = __ldg(bias + col), by = __ldg(bias + col + 1);
            int r0 = m0 + mbase + mt * 16 + qr;
            if (r0 < M) {
                float2 o = make_float2(acc[mt][nt][0] + bx, acc[mt][nt][1] + by);
                *(float2*)(C + (size_t)r0 * NN + col) = o;
            }
            if (r0 + 8 < M) {
                float2 o = make_float2(acc[mt][nt][2] + bx, acc[mt][nt][3] + by);
                *(float2*)(C + (size_t)(r0 + 8) * NN + col) = o;
            }
        }
    }
}

// dual-panel GEMM: C1 = A@B1+b1 (128 wide -> g_h), C2 = A@B2+b2 (NN2 wide -> g_skip)
template <int NN2>
__global__ __launch_bounds__(256) void gemm_dual(
    const float* __restrict__ A_ext, int useGX,
    const float* __restrict__ B1, const float* __restrict__ bias1,
    const float* __restrict__ B2, const float* __restrict__ bias2, int M) {

    constexpr int BP2 = (NN2 == 128) ? 136 : 40;

    extern __shared__ char smch[];
    unsigned* sAh  = (unsigned*)smch;            // 128*68 u32 each
    unsigned* sAl  = sAh + 128 * 68;
    unsigned* sB1h = sAl + 128 * 68;
    unsigned* sB1l = sB1h + 128 * 68;
    unsigned* sB2h = sB1l + 128 * 68;
    unsigned* sB2l = sB2h + 128 * (BP2 / 2);

    const float* A = useGX ? g_x : A_ext;

    int tid = threadIdx.x;
    int m0 = blockIdx.x * 128;

    // load + split A (128 x 128)
#pragma unroll
    for (int it = 0; it < 16; it++) {
        int i = tid + it * 256;
        int r = i >> 5, c4 = (i & 31) << 2;
        float4 v = make_float4(0.f, 0.f, 0.f, 0.f);
        if (m0 + r < M) v = *(const float4*)(A + (size_t)(m0 + r) * 128 + c4);
        int w = r * 68 + (c4 >> 1);
        sAh[w]     = pack_hi(v.x, v.y);
        sAh[w + 1] = pack_hi(v.z, v.w);
        sAl[w]     = pack_lo(v.x, v.y);
        sAl[w + 1] = pack_lo(v.z, v.w);
    }
    load_split_B<128>(B1, sB1h, sB1l, tid);
    load_split_B<NN2>(B2, sB2h, sB2l, tid);
    __syncthreads();

    int warp = tid >> 5, lane = tid & 31;
    unsigned sAh_s  = (unsigned)__cvta_generic_to_shared(sAh);
    unsigned sAl_s  = (unsigned)__cvta_generic_to_shared(sAl);
    unsigned sB1h_s = (unsigned)__cvta_generic_to_shared(sB1h);
    unsigned sB1l_s = (unsigned)__cvta_generic_to_shared(sB1l);
    unsigned sB2h_s = (unsigned)__cvta_generic_to_shared(sB2h);
    unsigned sB2l_s = (unsigned)__cvta_generic_to_shared(sB2l);

    mma_panel<128>(sAh_s, sAl_s, sB1h_s, sB1l_s, g_h, bias1, M, m0, warp, lane);
    mma_panel<NN2>(sAh_s, sAl_s, sB2h_s, sB2l_s, g_skip, bias2, M, m0, warp, lane);
}

// ---------------- fused attention: plain exp (shift-invariant softmax), warp per node ----------------
__device__ __forceinline__ float lrelu(float v) {
    return fmaxf(v, 0.f) + 0.2f * fminf(v, 0.f);
}

__global__ __launch_bounds__(256) void attn_kernel(
    const float* __restrict__ att, const float* __restrict__ bias,
    int last, float* __restrict__ out) {

    int gw = (blockIdx.x * blockDim.x + threadIdx.x) >> 5;
    int lane = threadIdx.x & 31;
    if (gw >= NNODES) return;
    int n = gw;

    float4 att4 = ((const float4*)att)[lane];
    float4 hd4  = ((const float4*)(g_h + (size_t)n * HC))[lane];

    float denom = 0.f;
    float4 acc = make_float4(0.f, 0.f, 0.f, 0.f);

    int start = g_rowptr[n];
    int end   = g_rowptr[n + 1];

    for (int base = start; base < end; base += 32) {
        int cnt = min(32, end - base);
        int sidx = (lane < cnt) ? g_csr_src[base + lane] : 0;
        for (int e = 0; e < cnt; e++) {
            int s = __shfl_sync(0xffffffffu, sidx, e);
            float4 hs4 = *((const float4*)(g_h + (size_t)s * HC) + lane);

            float part = lrelu(hs4.x + hd4.x) * att4.x
                       + lrelu(hs4.y + hd4.y) * att4.y
                       + lrelu(hs4.z + hd4.z) * att4.z
                       + lrelu(hs4.w + hd4.w) * att4.w;
            part += __shfl_xor_sync(0xffffffffu, part, 1);
            part += __shfl_xor_sync(0xffffffffu, part, 2);
            part += __shfl_xor_sync(0xffffffffu, part, 4);

            float p = __expf(part);      // scores are O(1): no max-shift needed
            denom += p;
            acc.x += p * hs4.x;
            acc.y += p * hs4.y;
            acc.z += p * hs4.z;
            acc.w += p * hs4.w;
        }
    }

    float inv = 1.0f / fmaxf(denom, 1e-16f);

    if (!last) {
        float4 sk = ((const float4*)(g_skip + (size_t)n * HC))[lane];
        float4 b4 = ((const float4*)bias)[lane];
        float4 o;
        o.x = acc.x * inv + b4.x + sk.x;
        o.y = acc.y * inv + b4.y + sk.y;
        o.z = acc.z * inv + b4.z + sk.z;
        o.w = acc.w * inv + b4.w + sk.w;
        o.x = o.x > 0.f ? o.x : expm1f(o.x);
        o.y = o.y > 0.f ? o.y : expm1f(o.y);
        o.z = o.z > 0.f ? o.z : expm1f(o.z);
        o.w = o.w > 0.f ? o.w : expm1f(o.w);
        ((float4*)(g_x + (size_t)n * HC))[lane] = o;
    } else {
        float4 r;
        r.x = acc.x * inv; r.y = acc.y * inv; r.z = acc.z * inv; r.w = acc.w * inv;
        r.x += __shfl_xor_sync(0xffffffffu, r.x, 8);
        r.y += __shfl_xor_sync(0xffffffffu, r.y, 8);
        r.z += __shfl_xor_sync(0xffffffffu, r.z, 8);
        r.w += __shfl_xor_sync(0xffffffffu, r.w, 8);
        r.x += __shfl_xor_sync(0xffffffffu, r.x, 16);
        r.y += __shfl_xor_sync(0xffffffffu, r.y, 16);
        r.z += __shfl_xor_sync(0xffffffffu, r.z, 16);
        r.w += __shfl_xor_sync(0xffffffffu, r.w, 16);
        if (lane < 8) {
            float4 sk = ((const float4*)(g_skip + (size_t)n * CDIM))[lane];
            float4 b4 = ((const float4*)bias)[lane];
            float4 o;
            o.x = 0.25f * r.x + b4.x + sk.x;
            o.y = 0.25f * r.y + b4.y + sk.y;
            o.z = 0.25f * r.z + b4.z + sk.z;
            o.w = 0.25f * r.w + b4.w + sk.w;
            ((float4*)(out + (size_t)n * CDIM))[lane] = o;
        }
    }
}

// ---------------- launch ----------------
extern "C" void kernel_launch(void* const* d_in, const int* in_sizes, int n_in,
                              void* d_out, int out_size) {
    const float* x  = (const float*)d_in[0];
    const void*  ei = d_in[1];
    const float* W[3]    = {(const float*)d_in[2],  (const float*)d_in[8],  (const float*)d_in[14]};
    const float* linb[3] = {(const float*)d_in[3],  (const float*)d_in[9],  (const float*)d_in[15]};
    const float* att[3]  = {(const float*)d_in[4],  (const float*)d_in[10], (const float*)d_in[16]};
    const float* bias[3] = {(const float*)d_in[5],  (const float*)d_in[11], (const float*)d_in[17]};
    const float* sW[3]   = {(const float*)d_in[6],  (const float*)d_in[12], (const float*)d_in[18]};
    const float* sb[3]   = {(const float*)d_in[7],  (const float*)d_in[13], (const float*)d_in[19]};

    int node_blocks = (NNODES + 255) / 256;
    int edge_blocks = (NEDGES + 255) / 256;

    const int smem_dual128 = (128 * 68) * 4 * 6;                     // 208896
    const int smem_dual32  = (128 * 68) * 4 * 4 + (128 * 20) * 4 * 2; // 159744
    cudaFuncSetAttribute(gemm_dual<128>, cudaFuncAttributeMaxDynamicSharedMemorySize, smem_dual128);
    cudaFuncSetAttribute(gemm_dual<32>,  cudaFuncAttributeMaxDynamicSharedMemorySize, smem_dual32);

    // decode edges + build CSR (shared by all 3 layers)
    detect_kernel<<<1, 256>>>((const unsigned int*)ei);
    zero_deg_kernel<<<node_blocks, 256>>>();
    decode_hist_kernel<<<(2 * NEDGES + 255) / 256, 256>>>(ei);
    scan1_kernel<<<SCAN_BLOCKS, 256>>>();
    scan2_kernel<<<1, 256>>>();
    scan3_kernel<<<node_blocks, 256>>>();
    scatter_kernel<<<edge_blocks, 256>>>();

    const int M = NNODES;
    int gemm_blocks = (M + 127) / 128;   // 391
    int attn_blocks = (NNODES + 7) / 8;

    for (int l = 0; l < 3; l++) {
        int useGX = (l > 0) ? 1 : 0;
        if (l < 2)
            gemm_dual<128><<<gemm_blocks, 256, smem_dual128>>>(
                x, useGX, W[l], linb[l], sW[l], sb[l], M);
        else
            gemm_dual<32><<<gemm_blocks, 256, smem_dual32>>>(
                x, useGX, W[l], linb[l], sW[l], sb[l], M);

        attn_kernel<<<attn_blocks, 256>>>(att[l], bias[l], (l == 2) ? 1 : 0,
                                          (float*)d_out);
    }
}

// round 6
// speedup vs baseline: 3.3796x; 1.0855x over previous
#include <cuda_runtime.h>
#include <cuda_bf16.h>
#include <cstdint>

#define NNODES 50000
#define NEDGES 600000
#define HC 128
#define NH 4
#define CDIM 32
#define SCAN_BLOCKS ((NNODES + 255) / 256)   // 196

// ---------------- scratch (device globals; no allocation allowed) ----------------
__device__ float g_x[NNODES * HC];
__device__ float g_h[NNODES * HC];
__device__ float g_skip[NNODES * HC];
__device__ int   g_src[NEDGES];
__device__ int   g_dst[NEDGES];
__device__ int   g_deg[NNODES];
__device__ int   g_rowptr[NNODES + 1];
__device__ int   g_ptr[NNODES];
__device__ int   g_bsum[SCAN_BLOCKS];
__device__ int   g_csr_src[NEDGES];
__device__ int   g_is64;

// ---------------- edge_index dtype detection ----------------
__global__ void detect_kernel(const unsigned int* __restrict__ buf) {
    __shared__ int nz;
    if (threadIdx.x == 0) nz = 0;
    __syncthreads();
    if (buf[2 * threadIdx.x + 1] != 0u) atomicOr(&nz, 1);
    __syncthreads();
    if (threadIdx.x == 0) g_is64 = (nz == 0) ? 1 : 0;
}

__global__ void zero_deg_kernel() {
    int i = blockIdx.x * blockDim.x + threadIdx.x;
    if (i < NNODES) g_deg[i] = 0;
}

// decode edge_index AND histogram dst degrees in one pass
__global__ void decode_hist_kernel(const void* __restrict__ buf) {
    int i = blockIdx.x * blockDim.x + threadIdx.x;
    if (i >= 2 * NEDGES) return;
    int v;
    if (g_is64) v = (int)(((const long long*)buf)[i]);
    else        v = ((const int*)buf)[i];
    if (i < NEDGES) g_src[i] = v;
    else {
        g_dst[i - NEDGES] = v;
        atomicAdd(&g_deg[v], 1);
    }
}

// ---------------- CSR scan ----------------
__global__ void scan1_kernel() {
    __shared__ int sh[256];
    int i = blockIdx.x * 256 + threadIdx.x;
    int v = (i < NNODES) ? g_deg[i] : 0;
    sh[threadIdx.x] = v;
    __syncthreads();
#pragma unroll
    for (int off = 1; off < 256; off <<= 1) {
        int t = (threadIdx.x >= off) ? sh[threadIdx.x - off] : 0;
        __syncthreads();
        sh[threadIdx.x] += t;
        __syncthreads();
    }
    if (i < NNODES) g_rowptr[i + 1] = sh[threadIdx.x];
    if (threadIdx.x == 255) g_bsum[blockIdx.x] = sh[255];
}

__global__ void scan2_kernel() {
    __shared__ int sh[256];
    int v = (threadIdx.x < SCAN_BLOCKS) ? g_bsum[threadIdx.x] : 0;
    sh[threadIdx.x] = v;
    __syncthreads();
#pragma unroll
    for (int off = 1; off < 256; off <<= 1) {
        int t = (threadIdx.x >= off) ? sh[threadIdx.x - off] : 0;
        __syncthreads();
        sh[threadIdx.x] += t;
        __syncthreads();
    }
    if (threadIdx.x < SCAN_BLOCKS)
        g_bsum[threadIdx.x] = (threadIdx.x == 0) ? 0 : sh[threadIdx.x - 1];
}

// finalize rowptr and also initialize g_ptr (scatter cursors)
__global__ void scan3_kernel() {
    int i = blockIdx.x * blockDim.x + threadIdx.x;
    if (i == 0) { g_rowptr[0] = 0; g_ptr[0] = 0; }
    if (i < NNODES) {
        int v = g_rowptr[i + 1] + g_bsum[i >> 8];
        g_rowptr[i + 1] = v;
        if (i + 1 < NNODES) g_ptr[i + 1] = v;
    }
}

__global__ void scatter_kernel() {
    int e = blockIdx.x * blockDim.x + threadIdx.x;
    if (e >= NEDGES) return;
    int d = g_dst[e];
    int pos = atomicAdd(&g_ptr[d], 1);
    g_csr_src[pos] = g_src[e];
}

// ---------------- tensor-core GEMM helpers (split-bf16) ----------------
__device__ __forceinline__ unsigned pack_hi(float a, float b) {
    unsigned short ha = __bfloat16_as_ushort(__float2bfloat16(a));
    unsigned short hb = __bfloat16_as_ushort(__float2bfloat16(b));
    return (unsigned)ha | ((unsigned)hb << 16);
}
__device__ __forceinline__ unsigned pack_lo(float a, float b) {
    float ra = a - __bfloat162float(__float2bfloat16(a));
    float rb = b - __bfloat162float(__float2bfloat16(b));
    unsigned short la = __bfloat16_as_ushort(__float2bfloat16(ra));
    unsigned short lb = __bfloat16_as_ushort(__float2bfloat16(rb));
    return (unsigned)la | ((unsigned)lb << 16);
}
__device__ __forceinline__ void ldmx4(unsigned* r, unsigned addr) {
    asm volatile("ldmatrix.sync.aligned.m8n8.x4.shared.b16 {%0,%1,%2,%3}, [%4];"
                 : "=r"(r[0]), "=r"(r[1]), "=r"(r[2]), "=r"(r[3]) : "r"(addr));
}
__device__ __forceinline__ void ldmx4t(unsigned* r, unsigned addr) {
    asm volatile("ldmatrix.sync.aligned.m8n8.x4.trans.shared.b16 {%0,%1,%2,%3}, [%4];"
                 : "=r"(r[0]), "=r"(r[1]), "=r"(r[2]), "=r"(r[3]) : "r"(addr));
}
__device__ __forceinline__ void mma_bf16(float* c, const unsigned* a, const unsigned* b) {
    asm volatile(
        "mma.sync.aligned.m16n8k16.row.col.f32.bf16.bf16.f32 "
        "{%0,%1,%2,%3}, {%4,%5,%6,%7}, {%8,%9}, {%0,%1,%2,%3};"
        : "+f"(c[0]), "+f"(c[1]), "+f"(c[2]), "+f"(c[3])
        : "r"(a[0]), "r"(a[1]), "r"(a[2]), "r"(a[3]), "r"(b[0]), "r"(b[1]));
}

#define AP 136   // A smem pitch (bf16 elems)

template <int NN>
__device__ __forceinline__ void load_split_B(const float* __restrict__ B,
                                             unsigned* sBh, unsigned* sBl, int tid) {
    constexpr int BP = (NN == 128) ? 136 : 40;
#pragma unroll
    for (int it = 0; it < 128 * (NN / 4) / 256; it++) {
        int i = tid + it * 256;
        int k = i / (NN / 4), n4 = (i % (NN / 4)) << 2;
        float4 v = *(const float4*)(B + (size_t)k * NN + n4);
        int w = k * (BP / 2) + (n4 >> 1);
        sBh[w]     = pack_hi(v.x, v.y);
        sBh[w + 1] = pack_hi(v.z, v.w);
        sBl[w]     = pack_lo(v.x, v.y);
        sBl[w + 1] = pack_lo(v.z, v.w);
    }
}

template <int NN>
__device__ __forceinline__ void mma_panel(
    unsigned sAh_s, unsigned sAl_s, unsigned sBh_s, unsigned sBl_s,
    float* __restrict__ C, const float* __restrict__ bias,
    int M, int m0, int warp, int lane) {

    constexpr int WARPS_N = (NN == 128) ? 4 : 1;
    constexpr int WARPS_M = 8 / WARPS_N;     // 2 or 8
    constexpr int WTM = 128 / WARPS_M;       // 64 or 16
    constexpr int MT = WTM / 16;             // 4 or 1
    constexpr int NT = 4;
    constexpr int BP = (NN == 128) ? 136 : 40;

    int wm = warp % WARPS_M, wn = warp / WARPS_M;
    int mbase = wm * WTM;
    int nbase = wn * 32;
    int qr = lane >> 2, qc = lane & 3;

    int aRow = mbase + (lane & 15);
    int aKof = (lane >> 4) << 3;
    unsigned aOff = (unsigned)((aRow * AP + aKof) * 2);
    int bK   = lane & 15;
    int bNof = nbase + ((lane >> 4) << 3);
    unsigned bOff = (unsigned)((bK * BP + bNof) * 2);

    float acc[MT][NT][4];
#pragma unroll
    for (int i = 0; i < MT; i++)
#pragma unroll
        for (int j = 0; j < NT; j++)
#pragma unroll
            for (int q = 0; q < 4; q++) acc[i][j][q] = 0.f;

#pragma unroll
    for (int ks = 0; ks < 8; ks++) {
        int k0 = ks * 16;

        unsigned ah[MT][4], al[MT][4];
#pragma unroll
        for (int mt = 0; mt < MT; mt++) {
            unsigned off = aOff + (unsigned)((mt * 16 * AP + k0) * 2);
            ldmx4(ah[mt], sAh_s + off);
            ldmx4(al[mt], sAl_s + off);
        }
        unsigned bh[NT][2], bl[NT][2];
#pragma unroll
        for (int np = 0; np < NT / 2; np++) {
            unsigned off = bOff + (unsigned)((k0 * BP + np * 16) * 2);
            unsigned t[4];
            ldmx4t(t, sBh_s + off);
            bh[2 * np][0] = t[0]; bh[2 * np][1] = t[1];
            bh[2 * np + 1][0] = t[2]; bh[2 * np + 1][1] = t[3];
            ldmx4t(t, sBl_s + off);
            bl[2 * np][0] = t[0]; bl[2 * np][1] = t[1];
            bl[2 * np + 1][0] = t[2]; bl[2 * np + 1][1] = t[3];
        }
#pragma unroll
        for (int mt = 0; mt < MT; mt++)
#pragma unroll
            for (int nt = 0; nt < NT; nt++) {
                mma_bf16(acc[mt][nt], ah[mt], bh[nt]);
                mma_bf16(acc[mt][nt], al[mt], bh[nt]);
                mma_bf16(acc[mt][nt], ah[mt], bl[nt]);
            }
    }

#pragma unroll
    for (int mt = 0; mt < MT; mt++) {
#pragma unroll
        for (int nt = 0; nt < NT; nt++) {
            int col = nbase + nt * 8 + 2 * qc;
            float bx = __ldg(bias + col), by = __ldg(bias + col + 1);
            int r0 = m0 + mbase + mt * 16 + qr;
            if (r0 < M) {
                float2 o = make_float2(acc[mt][nt][0] + bx, acc[mt][nt][1] + by);
                *(float2*)(C + (size_t)r0 * NN + col) = o;
            }
            if (r0 + 8 < M) {
                float2 o = make_float2(acc[mt][nt][2] + bx, acc[mt][nt][3] + by);
                *(float2*)(C + (size_t)(r0 + 8) * NN + col) = o;
            }
        }
    }
}

// dual-panel GEMM: C1 = A@B1+b1 (128 wide -> g_h), C2 = A@B2+b2 (NN2 wide -> g_skip)
template <int NN2>
__global__ __launch_bounds__(256) void gemm_dual(
    const float* __restrict__ A_ext, int useGX,
    const float* __restrict__ B1, const float* __restrict__ bias1,
    const float* __restrict__ B2, const float* __restrict__ bias2, int M) {

    constexpr int BP2 = (NN2 == 128) ? 136 : 40;

    extern __shared__ char smch[];
    unsigned* sAh  = (unsigned*)smch;            // 128*68 u32 each
    unsigned* sAl  = sAh + 128 * 68;
    unsigned* sB1h = sAl + 128 * 68;
    unsigned* sB1l = sB1h + 128 * 68;
    unsigned* sB2h = sB1l + 128 * 68;
    unsigned* sB2l = sB2h + 128 * (BP2 / 2);

    const float* A = useGX ? g_x : A_ext;

    int tid = threadIdx.x;
    int m0 = blockIdx.x * 128;

    // load + split A (128 x 128)
#pragma unroll
    for (int it = 0; it < 16; it++) {
        int i = tid + it * 256;
        int r = i >> 5, c4 = (i & 31) << 2;
        float4 v = make_float4(0.f, 0.f, 0.f, 0.f);
        if (m0 + r < M) v = *(const float4*)(A + (size_t)(m0 + r) * 128 + c4);
        int w = r * 68 + (c4 >> 1);
        sAh[w]     = pack_hi(v.x, v.y);
        sAh[w + 1] = pack_hi(v.z, v.w);
        sAl[w]     = pack_lo(v.x, v.y);
        sAl[w + 1] = pack_lo(v.z, v.w);
    }
    load_split_B<128>(B1, sB1h, sB1l, tid);
    load_split_B<NN2>(B2, sB2h, sB2l, tid);
    __syncthreads();

    int warp = tid >> 5, lane = tid & 31;
    unsigned sAh_s  = (unsigned)__cvta_generic_to_shared(sAh);
    unsigned sAl_s  = (unsigned)__cvta_generic_to_shared(sAl);
    unsigned sB1h_s = (unsigned)__cvta_generic_to_shared(sB1h);
    unsigned sB1l_s = (unsigned)__cvta_generic_to_shared(sB1l);
    unsigned sB2h_s = (unsigned)__cvta_generic_to_shared(sB2h);
    unsigned sB2l_s = (unsigned)__cvta_generic_to_shared(sB2l);

    mma_panel<128>(sAh_s, sAl_s, sB1h_s, sB1l_s, g_h, bias1, M, m0, warp, lane);
    mma_panel<NN2>(sAh_s, sAl_s, sB2h_s, sB2l_s, g_skip, bias2, M, m0, warp, lane);
}

// ---------------- fused attention: plain exp softmax, warp per node, 2-edge unroll ----------------
__device__ __forceinline__ float lrelu(float v) {
    return fmaxf(v, 0.f) + 0.2f * fminf(v, 0.f);
}

__global__ __launch_bounds__(256) void attn_kernel(
    const float* __restrict__ att, const float* __restrict__ bias,
    int last, float* __restrict__ out) {

    int gw = (blockIdx.x * blockDim.x + threadIdx.x) >> 5;
    int lane = threadIdx.x & 31;
    if (gw >= NNODES) return;
    int n = gw;

    float4 att4 = ((const float4*)att)[lane];
    float4 hd4  = ((const float4*)(g_h + (size_t)n * HC))[lane];

    float denom = 0.f;
    float4 acc = make_float4(0.f, 0.f, 0.f, 0.f);

    int start = g_rowptr[n];
    int end   = g_rowptr[n + 1];

    for (int base = start; base < end; base += 32) {
        int cnt = min(32, end - base);
        int sidx = (lane < cnt) ? g_csr_src[base + lane] : 0;
        int e = 0;
        for (; e + 2 <= cnt; e += 2) {
            int s0 = __shfl_sync(0xffffffffu, sidx, e);
            int s1 = __shfl_sync(0xffffffffu, sidx, e + 1);
            float4 h0 = *((const float4*)(g_h + (size_t)s0 * HC) + lane);
            float4 h1 = *((const float4*)(g_h + (size_t)s1 * HC) + lane);

            float p0 = lrelu(h0.x + hd4.x) * att4.x
                     + lrelu(h0.y + hd4.y) * att4.y
                     + lrelu(h0.z + hd4.z) * att4.z
                     + lrelu(h0.w + hd4.w) * att4.w;
            float p1 = lrelu(h1.x + hd4.x) * att4.x
                     + lrelu(h1.y + hd4.y) * att4.y
                     + lrelu(h1.z + hd4.z) * att4.z
                     + lrelu(h1.w + hd4.w) * att4.w;
            p0 += __shfl_xor_sync(0xffffffffu, p0, 1);
            p1 += __shfl_xor_sync(0xffffffffu, p1, 1);
            p0 += __shfl_xor_sync(0xffffffffu, p0, 2);
            p1 += __shfl_xor_sync(0xffffffffu, p1, 2);
            p0 += __shfl_xor_sync(0xffffffffu, p0, 4);
            p1 += __shfl_xor_sync(0xffffffffu, p1, 4);

            float w0 = __expf(p0);
            float w1 = __expf(p1);
            denom += w0 + w1;
            acc.x += w0 * h0.x + w1 * h1.x;
            acc.y += w0 * h0.y + w1 * h1.y;
            acc.z += w0 * h0.z + w1 * h1.z;
            acc.w += w0 * h0.w + w1 * h1.w;
        }
        if (e < cnt) {
            int s0 = __shfl_sync(0xffffffffu, sidx, e);
            float4 h0 = *((const float4*)(g_h + (size_t)s0 * HC) + lane);
            float p0 = lrelu(h0.x + hd4.x) * att4.x
                     + lrelu(h0.y + hd4.y) * att4.y
                     + lrelu(h0.z + hd4.z) * att4.z
                     + lrelu(h0.w + hd4.w) * att4.w;
            p0 += __shfl_xor_sync(0xffffffffu, p0, 1);
            p0 += __shfl_xor_sync(0xffffffffu, p0, 2);
            p0 += __shfl_xor_sync(0xffffffffu, p0, 4);
            float w0 = __expf(p0);
            denom += w0;
            acc.x += w0 * h0.x;
            acc.y += w0 * h0.y;
            acc.z += w0 * h0.z;
            acc.w += w0 * h0.w;
        }
    }

    float inv = 1.0f / fmaxf(denom, 1e-16f);

    if (!last) {
        float4 sk = ((const float4*)(g_skip + (size_t)n * HC))[lane];
        float4 b4 = ((const float4*)bias)[lane];
        float4 o;
        o.x = acc.x * inv + b4.x + sk.x;
        o.y = acc.y * inv + b4.y + sk.y;
        o.z = acc.z * inv + b4.z + sk.z;
        o.w = acc.w * inv + b4.w + sk.w;
        o.x = o.x > 0.f ? o.x : expm1f(o.x);
        o.y = o.y > 0.f ? o.y : expm1f(o.y);
        o.z = o.z > 0.f ? o.z : expm1f(o.z);
        o.w = o.w > 0.f ? o.w : expm1f(o.w);
        ((float4*)(g_x + (size_t)n * HC))[lane] = o;
    } else {
        float4 r;
        r.x = acc.x * inv; r.y = acc.y * inv; r.z = acc.z * inv; r.w = acc.w * inv;
        r.x += __shfl_xor_sync(0xffffffffu, r.x, 8);
        r.y += __shfl_xor_sync(0xffffffffu, r.y, 8);
        r.z += __shfl_xor_sync(0xffffffffu, r.z, 8);
        r.w += __shfl_xor_sync(0xffffffffu, r.w, 8);
        r.x += __shfl_xor_sync(0xffffffffu, r.x, 16);
        r.y += __shfl_xor_sync(0xffffffffu, r.y, 16);
        r.z += __shfl_xor_sync(0xffffffffu, r.z, 16);
        r.w += __shfl_xor_sync(0xffffffffu, r.w, 16);
        if (lane < 8) {
            float4 sk = ((const float4*)(g_skip + (size_t)n * CDIM))[lane];
            float4 b4 = ((const float4*)bias)[lane];
            float4 o;
            o.x = 0.25f * r.x + b4.x + sk.x;
            o.y = 0.25f * r.y + b4.y + sk.y;
            o.z = 0.25f * r.z + b4.z + sk.z;
            o.w = 0.25f * r.w + b4.w + sk.w;
            ((float4*)(out + (size_t)n * CDIM))[lane] = o;
        }
    }
}

// ---------------- launch ----------------
extern "C" void kernel_launch(void* const* d_in, const int* in_sizes, int n_in,
                              void* d_out, int out_size) {
    const float* x  = (const float*)d_in[0];
    const void*  ei = d_in[1];
    const float* W[3]    = {(const float*)d_in[2],  (const float*)d_in[8],  (const float*)d_in[14]};
    const float* linb[3] = {(const float*)d_in[3],  (const float*)d_in[9],  (const float*)d_in[15]};
    const float* att[3]  = {(const float*)d_in[4],  (const float*)d_in[10], (const float*)d_in[16]};
    const float* bias[3] = {(const float*)d_in[5],  (const float*)d_in[11], (const float*)d_in[17]};
    const float* sW[3]   = {(const float*)d_in[6],  (const float*)d_in[12], (const float*)d_in[18]};
    const float* sb[3]   = {(const float*)d_in[7],  (const float*)d_in[13], (const float*)d_in[19]};

    // one-time side stream + events (host-side objects only; no device memory)
    static cudaStream_t s_side = nullptr;
    static cudaEvent_t  s_fork = nullptr, s_join = nullptr;
    if (!s_side) {
        cudaStreamCreateWithFlags(&s_side, cudaStreamNonBlocking);
        cudaEventCreateWithFlags(&s_fork, cudaEventDisableTiming);
        cudaEventCreateWithFlags(&s_join, cudaEventDisableTiming);
    }

    int node_blocks = (NNODES + 255) / 256;
    int edge_blocks = (NEDGES + 255) / 256;

    const int smem_dual128 = (128 * 68) * 4 * 6;                      // 208896
    const int smem_dual32  = (128 * 68) * 4 * 4 + (128 * 20) * 4 * 2; // 159744
    cudaFuncSetAttribute(gemm_dual<128>, cudaFuncAttributeMaxDynamicSharedMemorySize, smem_dual128);
    cudaFuncSetAttribute(gemm_dual<32>,  cudaFuncAttributeMaxDynamicSharedMemorySize, smem_dual32);

    const int M = NNODES;
    int gemm_blocks = (M + 127) / 128;   // 391
    int attn_blocks = (NNODES + 7) / 8;

    // fork: CSR build chain on side stream, concurrent with layer-0 GEMM
    cudaEventRecord(s_fork, 0);
    cudaStreamWaitEvent(s_side, s_fork, 0);

    detect_kernel<<<1, 256, 0, s_side>>>((const unsigned int*)ei);
    zero_deg_kernel<<<node_blocks, 256, 0, s_side>>>();
    decode_hist_kernel<<<(2 * NEDGES + 255) / 256, 256, 0, s_side>>>(ei);
    scan1_kernel<<<SCAN_BLOCKS, 256, 0, s_side>>>();
    scan2_kernel<<<1, 256, 0, s_side>>>();
    scan3_kernel<<<node_blocks, 256, 0, s_side>>>();
    scatter_kernel<<<edge_blocks, 256, 0, s_side>>>();

    // layer-0 GEMM on main stream (independent of CSR)
    gemm_dual<128><<<gemm_blocks, 256, smem_dual128>>>(
        x, 0, W[0], linb[0], sW[0], sb[0], M);

    // join before attention needs the CSR
    cudaEventRecord(s_join, s_side);
    cudaStreamWaitEvent(0, s_join, 0);

    attn_kernel<<<attn_blocks, 256>>>(att[0], bias[0], 0, (float*)d_out);

    for (int l = 1; l < 3; l++) {
        if (l < 2)
            gemm_dual<128><<<gemm_blocks, 256, smem_dual128>>>(
                x, 1, W[l], linb[l], sW[l], sb[l], M);
        else
            gemm_dual<32><<<gemm_blocks, 256, smem_dual32>>>(
                x, 1, W[l], linb[l], sW[l], sb[l], M);

        attn_kernel<<<attn_blocks, 256>>>(att[l], bias[l], (l == 2) ? 1 : 0,
                                          (float*)d_out);
    }
}

// round 7
// speedup vs baseline: 3.4369x; 1.0170x over previous
#include <cuda_runtime.h>
#include <cuda_bf16.h>
#include <cstdint>

#define NNODES 50000
#define NEDGES 600000
#define HC 128
#define NH 4
#define CDIM 32
#define SCAN_BLOCKS ((NNODES + 255) / 256)   // 196

// ---------------- scratch (device globals; no allocation allowed) ----------------
__device__ float g_x[NNODES * HC];
__device__ float g_h[NNODES * HC];
__device__ float g_skip[NNODES * HC];
__device__ int   g_src[NEDGES];
__device__ int   g_dst[NEDGES];
__device__ int   g_deg[NNODES];
__device__ int   g_rowptr[NNODES + 1];
__device__ int   g_ptr[NNODES];
__device__ int   g_bsum[SCAN_BLOCKS];
__device__ int   g_csr_src[NEDGES];
__device__ int   g_is64;

// ---------------- edge_index dtype detection ----------------
__global__ void detect_kernel(const unsigned int* __restrict__ buf) {
    __shared__ int nz;
    if (threadIdx.x == 0) nz = 0;
    __syncthreads();
    if (buf[2 * threadIdx.x + 1] != 0u) atomicOr(&nz, 1);
    __syncthreads();
    if (threadIdx.x == 0) g_is64 = (nz == 0) ? 1 : 0;
}

__global__ void zero_deg_kernel() {
    int i = blockIdx.x * blockDim.x + threadIdx.x;
    if (i < NNODES) g_deg[i] = 0;
}

// decode edge_index AND histogram dst degrees; 2 elements per thread (vectorized)
__global__ void decode_hist_kernel(const void* __restrict__ buf) {
    int t = blockIdx.x * blockDim.x + threadIdx.x;
    int i0 = 2 * t;                       // element index (0 .. 2*NEDGES-1), 2 per thread
    if (i0 >= 2 * NEDGES) return;
    int v0, v1;
    if (g_is64) {
        longlong2 p = ((const longlong2*)buf)[t];
        v0 = (int)p.x; v1 = (int)p.y;
    } else {
        int2 p = ((const int2*)buf)[t];
        v0 = p.x; v1 = p.y;
    }
#pragma unroll
    for (int q = 0; q < 2; q++) {
        int i = i0 + q;
        int v = q ? v1 : v0;
        if (i < NEDGES) g_src[i] = v;
        else if (i < 2 * NEDGES) {
            g_dst[i - NEDGES] = v;
            atomicAdd(&g_deg[v], 1);
        }
    }
}

// ---------------- CSR scan ----------------
__global__ void scan1_kernel() {
    __shared__ int sh[256];
    int i = blockIdx.x * 256 + threadIdx.x;
    int v = (i < NNODES) ? g_deg[i] : 0;
    sh[threadIdx.x] = v;
    __syncthreads();
#pragma unroll
    for (int off = 1; off < 256; off <<= 1) {
        int t = (threadIdx.x >= off) ? sh[threadIdx.x - off] : 0;
        __syncthreads();
        sh[threadIdx.x] += t;
        __syncthreads();
    }
    if (i < NNODES) g_rowptr[i + 1] = sh[threadIdx.x];
    if (threadIdx.x == 255) g_bsum[blockIdx.x] = sh[255];
}

__global__ void scan2_kernel() {
    __shared__ int sh[256];
    int v = (threadIdx.x < SCAN_BLOCKS) ? g_bsum[threadIdx.x] : 0;
    sh[threadIdx.x] = v;
    __syncthreads();
#pragma unroll
    for (int off = 1; off < 256; off <<= 1) {
        int t = (threadIdx.x >= off) ? sh[threadIdx.x - off] : 0;
        __syncthreads();
        sh[threadIdx.x] += t;
        __syncthreads();
    }
    if (threadIdx.x < SCAN_BLOCKS)
        g_bsum[threadIdx.x] = (threadIdx.x == 0) ? 0 : sh[threadIdx.x - 1];
}

// finalize rowptr and also initialize g_ptr (scatter cursors)
__global__ void scan3_kernel() {
    int i = blockIdx.x * blockDim.x + threadIdx.x;
    if (i == 0) { g_rowptr[0] = 0; g_ptr[0] = 0; }
    if (i < NNODES) {
        int v = g_rowptr[i + 1] + g_bsum[i >> 8];
        g_rowptr[i + 1] = v;
        if (i + 1 < NNODES) g_ptr[i + 1] = v;
    }
}

__global__ void scatter_kernel() {
    int e = blockIdx.x * blockDim.x + threadIdx.x;
    if (e >= NEDGES) return;
    int d = g_dst[e];
    int pos = atomicAdd(&g_ptr[d], 1);
    g_csr_src[pos] = g_src[e];
}

// ---------------- tensor-core GEMM helpers (split-bf16) ----------------
__device__ __forceinline__ unsigned pack_hi(float a, float b) {
    unsigned short ha = __bfloat16_as_ushort(__float2bfloat16(a));
    unsigned short hb = __bfloat16_as_ushort(__float2bfloat16(b));
    return (unsigned)ha | ((unsigned)hb << 16);
}
__device__ __forceinline__ unsigned pack_lo(float a, float b) {
    float ra = a - __bfloat162float(__float2bfloat16(a));
    float rb = b - __bfloat162float(__float2bfloat16(b));
    unsigned short la = __bfloat16_as_ushort(__float2bfloat16(ra));
    unsigned short lb = __bfloat16_as_ushort(__float2bfloat16(rb));
    return (unsigned)la | ((unsigned)lb << 16);
}
__device__ __forceinline__ void ldmx4(unsigned* r, unsigned addr) {
    asm volatile("ldmatrix.sync.aligned.m8n8.x4.shared.b16 {%0,%1,%2,%3}, [%4];"
                 : "=r"(r[0]), "=r"(r[1]), "=r"(r[2]), "=r"(r[3]) : "r"(addr));
}
__device__ __forceinline__ void ldmx4t(unsigned* r, unsigned addr) {
    asm volatile("ldmatrix.sync.aligned.m8n8.x4.trans.shared.b16 {%0,%1,%2,%3}, [%4];"
                 : "=r"(r[0]), "=r"(r[1]), "=r"(r[2]), "=r"(r[3]) : "r"(addr));
}
__device__ __forceinline__ void mma_bf16(float* c, const unsigned* a, const unsigned* b) {
    asm volatile(
        "mma.sync.aligned.m16n8k16.row.col.f32.bf16.bf16.f32 "
        "{%0,%1,%2,%3}, {%4,%5,%6,%7}, {%8,%9}, {%0,%1,%2,%3};"
        : "+f"(c[0]), "+f"(c[1]), "+f"(c[2]), "+f"(c[3])
        : "r"(a[0]), "r"(a[1]), "r"(a[2]), "r"(a[3]), "r"(b[0]), "r"(b[1]));
}

#define AP 136   // A smem pitch (bf16 elems)

template <int NN>
__device__ __forceinline__ void load_split_B(const float* __restrict__ B,
                                             unsigned* sBh, unsigned* sBl, int tid) {
    constexpr int BP = (NN == 128) ? 136 : 40;
#pragma unroll
    for (int it = 0; it < 128 * (NN / 4) / 256; it++) {
        int i = tid + it * 256;
        int k = i / (NN / 4), n4 = (i % (NN / 4)) << 2;
        float4 v = *(const float4*)(B + (size_t)k * NN + n4);
        int w = k * (BP / 2) + (n4 >> 1);
        sBh[w]     = pack_hi(v.x, v.y);
        sBh[w + 1] = pack_hi(v.z, v.w);
        sBl[w]     = pack_lo(v.x, v.y);
        sBl[w + 1] = pack_lo(v.z, v.w);
    }
}

template <int NN>
__device__ __forceinline__ void mma_panel(
    unsigned sAh_s, unsigned sAl_s, unsigned sBh_s, unsigned sBl_s,
    float* __restrict__ C, const float* __restrict__ bias,
    int M, int m0, int warp, int lane) {

    constexpr int WARPS_N = (NN == 128) ? 4 : 1;
    constexpr int WARPS_M = 8 / WARPS_N;     // 2 or 8
    constexpr int WTM = 128 / WARPS_M;       // 64 or 16
    constexpr int MT = WTM / 16;             // 4 or 1
    constexpr int NT = 4;
    constexpr int BP = (NN == 128) ? 136 : 40;

    int wm = warp % WARPS_M, wn = warp / WARPS_M;
    int mbase = wm * WTM;
    int nbase = wn * 32;
    int qr = lane >> 2, qc = lane & 3;

    int aRow = mbase + (lane & 15);
    int aKof = (lane >> 4) << 3;
    unsigned aOff = (unsigned)((aRow * AP + aKof) * 2);
    int bK   = lane & 15;
    int bNof = nbase + ((lane >> 4) << 3);
    unsigned bOff = (unsigned)((bK * BP + bNof) * 2);

    float acc[MT][NT][4];
#pragma unroll
    for (int i = 0; i < MT; i++)
#pragma unroll
        for (int j = 0; j < NT; j++)
#pragma unroll
            for (int q = 0; q < 4; q++) acc[i][j][q] = 0.f;

#pragma unroll
    for (int ks = 0; ks < 8; ks++) {
        int k0 = ks * 16;

        unsigned ah[MT][4], al[MT][4];
#pragma unroll
        for (int mt = 0; mt < MT; mt++) {
            unsigned off = aOff + (unsigned)((mt * 16 * AP + k0) * 2);
            ldmx4(ah[mt], sAh_s + off);
            ldmx4(al[mt], sAl_s + off);
        }
        unsigned bh[NT][2], bl[NT][2];
#pragma unroll
        for (int np = 0; np < NT / 2; np++) {
            unsigned off = bOff + (unsigned)((k0 * BP + np * 16) * 2);
            unsigned t[4];
            ldmx4t(t, sBh_s + off);
            bh[2 * np][0] = t[0]; bh[2 * np][1] = t[1];
            bh[2 * np + 1][0] = t[2]; bh[2 * np + 1][1] = t[3];
            ldmx4t(t, sBl_s + off);
            bl[2 * np][0] = t[0]; bl[2 * np][1] = t[1];
            bl[2 * np + 1][0] = t[2]; bl[2 * np + 1][1] = t[3];
        }
#pragma unroll
        for (int mt = 0; mt < MT; mt++)
#pragma unroll
            for (int nt = 0; nt < NT; nt++) {
                mma_bf16(acc[mt][nt], ah[mt], bh[nt]);
                mma_bf16(acc[mt][nt], al[mt], bh[nt]);
                mma_bf16(acc[mt][nt], ah[mt], bl[nt]);
            }
    }

#pragma unroll
    for (int mt = 0; mt < MT; mt++) {
#pragma unroll
        for (int nt = 0; nt < NT; nt++) {
            int col = nbase + nt * 8 + 2 * qc;
            float bx = __ldg(bias + col), by = __ldg(bias + col + 1);
            int r0 = m0 + mbase + mt * 16 + qr;
            if (r0 < M) {
                float2 o = make_float2(acc[mt][nt][0] + bx, acc[mt][nt][1] + by);
                *(float2*)(C + (size_t)r0 * NN + col) = o;
            }
            if (r0 + 8 < M) {
                float2 o = make_float2(acc[mt][nt][2] + bx, acc[mt][nt][3] + by);
                *(float2*)(C + (size_t)(r0 + 8) * NN + col) = o;
            }
        }
    }
}

// persistent dual-panel GEMM: B panels split once per block; grid-stride over A chunks
template <int NN2>
__global__ __launch_bounds__(256) void gemm_dual_pers(
    const float* __restrict__ A_ext, int useGX,
    const float* __restrict__ B1, const float* __restrict__ bias1,
    const float* __restrict__ B2, const float* __restrict__ bias2,
    int M, int nchunks) {

    constexpr int BP2 = (NN2 == 128) ? 136 : 40;

    extern __shared__ char smch[];
    unsigned* sAh  = (unsigned*)smch;            // 128*68 u32 each
    unsigned* sAl  = sAh + 128 * 68;
    unsigned* sB1h = sAl + 128 * 68;
    unsigned* sB1l = sB1h + 128 * 68;
    unsigned* sB2h = sB1l + 128 * 68;
    unsigned* sB2l = sB2h + 128 * (BP2 / 2);

    const float* A = useGX ? g_x : A_ext;

    int tid = threadIdx.x;
    int warp = tid >> 5, lane = tid & 31;

    // load + split B panels once
    load_split_B<128>(B1, sB1h, sB1l, tid);
    load_split_B<NN2>(B2, sB2h, sB2l, tid);

    unsigned sAh_s  = (unsigned)__cvta_generic_to_shared(sAh);
    unsigned sAl_s  = (unsigned)__cvta_generic_to_shared(sAl);
    unsigned sB1h_s = (unsigned)__cvta_generic_to_shared(sB1h);
    unsigned sB1l_s = (unsigned)__cvta_generic_to_shared(sB1l);
    unsigned sB2h_s = (unsigned)__cvta_generic_to_shared(sB2h);
    unsigned sB2l_s = (unsigned)__cvta_generic_to_shared(sB2l);

    for (int chunk = blockIdx.x; chunk < nchunks; chunk += gridDim.x) {
        int m0 = chunk * 128;

        __syncthreads();   // previous MMA done reading sA (and B ready on 1st iter)
#pragma unroll
        for (int it = 0; it < 16; it++) {
            int i = tid + it * 256;
            int r = i >> 5, c4 = (i & 31) << 2;
            float4 v = make_float4(0.f, 0.f, 0.f, 0.f);
            if (m0 + r < M) v = *(const float4*)(A + (size_t)(m0 + r) * 128 + c4);
            int w = r * 68 + (c4 >> 1);
            sAh[w]     = pack_hi(v.x, v.y);
            sAh[w + 1] = pack_hi(v.z, v.w);
            sAl[w]     = pack_lo(v.x, v.y);
            sAl[w + 1] = pack_lo(v.z, v.w);
        }
        __syncthreads();

        mma_panel<128>(sAh_s, sAl_s, sB1h_s, sB1l_s, g_h, bias1, M, m0, warp, lane);
        mma_panel<NN2>(sAh_s, sAl_s, sB2h_s, sB2l_s, g_skip, bias2, M, m0, warp, lane);
    }
}

// ---------------- fused attention: plain exp softmax, warp per node, 4-edge unroll ----------------
__device__ __forceinline__ float lrelu(float v) {
    return fmaxf(v, 0.f) + 0.2f * fminf(v, 0.f);
}

__global__ __launch_bounds__(256) void attn_kernel(
    const float* __restrict__ att, const float* __restrict__ bias,
    int last, float* __restrict__ out) {

    int gw = (blockIdx.x * blockDim.x + threadIdx.x) >> 5;
    int lane = threadIdx.x & 31;
    if (gw >= NNODES) return;
    int n = gw;

    float4 att4 = ((const float4*)att)[lane];
    float4 hd4  = ((const float4*)(g_h + (size_t)n * HC))[lane];

    float denom = 0.f;
    float4 acc = make_float4(0.f, 0.f, 0.f, 0.f);

    int start = g_rowptr[n];
    int end   = g_rowptr[n + 1];

    for (int base = start; base < end; base += 32) {
        int cnt = min(32, end - base);
        int sidx = (lane < cnt) ? g_csr_src[base + lane] : 0;
        int e = 0;
        for (; e + 4 <= cnt; e += 4) {
            int s0 = __shfl_sync(0xffffffffu, sidx, e);
            int s1 = __shfl_sync(0xffffffffu, sidx, e + 1);
            int s2 = __shfl_sync(0xffffffffu, sidx, e + 2);
            int s3 = __shfl_sync(0xffffffffu, sidx, e + 3);
            float4 h0 = *((const float4*)(g_h + (size_t)s0 * HC) + lane);
            float4 h1 = *((const float4*)(g_h + (size_t)s1 * HC) + lane);
            float4 h2 = *((const float4*)(g_h + (size_t)s2 * HC) + lane);
            float4 h3 = *((const float4*)(g_h + (size_t)s3 * HC) + lane);

            float p0 = lrelu(h0.x + hd4.x) * att4.x + lrelu(h0.y + hd4.y) * att4.y
                     + lrelu(h0.z + hd4.z) * att4.z + lrelu(h0.w + hd4.w) * att4.w;
            float p1 = lrelu(h1.x + hd4.x) * att4.x + lrelu(h1.y + hd4.y) * att4.y
                     + lrelu(h1.z + hd4.z) * att4.z + lrelu(h1.w + hd4.w) * att4.w;
            float p2 = lrelu(h2.x + hd4.x) * att4.x + lrelu(h2.y + hd4.y) * att4.y
                     + lrelu(h2.z + hd4.z) * att4.z + lrelu(h2.w + hd4.w) * att4.w;
            float p3 = lrelu(h3.x + hd4.x) * att4.x + lrelu(h3.y + hd4.y) * att4.y
                     + lrelu(h3.z + hd4.z) * att4.z + lrelu(h3.w + hd4.w) * att4.w;

            p0 += __shfl_xor_sync(0xffffffffu, p0, 1);
            p1 += __shfl_xor_sync(0xffffffffu, p1, 1);
            p2 += __shfl_xor_sync(0xffffffffu, p2, 1);
            p3 += __shfl_xor_sync(0xffffffffu, p3, 1);
            p0 += __shfl_xor_sync(0xffffffffu, p0, 2);
            p1 += __shfl_xor_sync(0xffffffffu, p1, 2);
            p2 += __shfl_xor_sync(0xffffffffu, p2, 2);
            p3 += __shfl_xor_sync(0xffffffffu, p3, 2);
            p0 += __shfl_xor_sync(0xffffffffu, p0, 4);
            p1 += __shfl_xor_sync(0xffffffffu, p1, 4);
            p2 += __shfl_xor_sync(0xffffffffu, p2, 4);
            p3 += __shfl_xor_sync(0xffffffffu, p3, 4);

            float w0 = __expf(p0);
            float w1 = __expf(p1);
            float w2 = __expf(p2);
            float w3 = __expf(p3);
            denom += (w0 + w1) + (w2 + w3);
            acc.x += w0 * h0.x + w1 * h1.x + w2 * h2.x + w3 * h3.x;
            acc.y += w0 * h0.y + w1 * h1.y + w2 * h2.y + w3 * h3.y;
            acc.z += w0 * h0.z + w1 * h1.z + w2 * h2.z + w3 * h3.z;
            acc.w += w0 * h0.w + w1 * h1.w + w2 * h2.w + w3 * h3.w;
        }
        for (; e < cnt; e++) {
            int s0 = __shfl_sync(0xffffffffu, sidx, e);
            float4 h0 = *((const float4*)(g_h + (size_t)s0 * HC) + lane);
            float p0 = lrelu(h0.x + hd4.x) * att4.x + lrelu(h0.y + hd4.y) * att4.y
                     + lrelu(h0.z + hd4.z) * att4.z + lrelu(h0.w + hd4.w) * att4.w;
            p0 += __shfl_xor_sync(0xffffffffu, p0, 1);
            p0 += __shfl_xor_sync(0xffffffffu, p0, 2);
            p0 += __shfl_xor_sync(0xffffffffu, p0, 4);
            float w0 = __expf(p0);
            denom += w0;
            acc.x += w0 * h0.x;
            acc.y += w0 * h0.y;
            acc.z += w0 * h0.z;
            acc.w += w0 * h0.w;
        }
    }

    float inv = 1.0f / fmaxf(denom, 1e-16f);

    if (!last) {
        float4 sk = ((const float4*)(g_skip + (size_t)n * HC))[lane];
        float4 b4 = ((const float4*)bias)[lane];
        float4 o;
        o.x = acc.x * inv + b4.x + sk.x;
        o.y = acc.y * inv + b4.y + sk.y;
        o.z = acc.z * inv + b4.z + sk.z;
        o.w = acc.w * inv + b4.w + sk.w;
        o.x = o.x > 0.f ? o.x : expm1f(o.x);
        o.y = o.y > 0.f ? o.y : expm1f(o.y);
        o.z = o.z > 0.f ? o.z : expm1f(o.z);
        o.w = o.w > 0.f ? o.w : expm1f(o.w);
        ((float4*)(g_x + (size_t)n * HC))[lane] = o;
    } else {
        float4 r;
        r.x = acc.x * inv; r.y = acc.y * inv; r.z = acc.z * inv; r.w = acc.w * inv;
        r.x += __shfl_xor_sync(0xffffffffu, r.x, 8);
        r.y += __shfl_xor_sync(0xffffffffu, r.y, 8);
        r.z += __shfl_xor_sync(0xffffffffu, r.z, 8);
        r.w += __shfl_xor_sync(0xffffffffu, r.w, 8);
        r.x += __shfl_xor_sync(0xffffffffu, r.x, 16);
        r.y += __shfl_xor_sync(0xffffffffu, r.y, 16);
        r.z += __shfl_xor_sync(0xffffffffu, r.z, 16);
        r.w += __shfl_xor_sync(0xffffffffu, r.w, 16);
        if (lane < 8) {
            float4 sk = ((const float4*)(g_skip + (size_t)n * CDIM))[lane];
            float4 b4 = ((const float4*)bias)[lane];
            float4 o;
            o.x = 0.25f * r.x + b4.x + sk.x;
            o.y = 0.25f * r.y + b4.y + sk.y;
            o.z = 0.25f * r.z + b4.z + sk.z;
            o.w = 0.25f * r.w + b4.w + sk.w;
            ((float4*)(out + (size_t)n * CDIM))[lane] = o;
        }
    }
}

// ---------------- launch ----------------
extern "C" void kernel_launch(void* const* d_in, const int* in_sizes, int n_in,
                              void* d_out, int out_size) {
    const float* x  = (const float*)d_in[0];
    const void*  ei = d_in[1];
    const float* W[3]    = {(const float*)d_in[2],  (const float*)d_in[8],  (const float*)d_in[14]};
    const float* linb[3] = {(const float*)d_in[3],  (const float*)d_in[9],  (const float*)d_in[15]};
    const float* att[3]  = {(const float*)d_in[4],  (const float*)d_in[10], (const float*)d_in[16]};
    const float* bias[3] = {(const float*)d_in[5],  (const float*)d_in[11], (const float*)d_in[17]};
    const float* sW[3]   = {(const float*)d_in[6],  (const float*)d_in[12], (const float*)d_in[18]};
    const float* sb[3]   = {(const float*)d_in[7],  (const float*)d_in[13], (const float*)d_in[19]};

    // one-time side stream + events + SM count (host-side objects only)
    static cudaStream_t s_side = nullptr;
    static cudaEvent_t  s_fork = nullptr, s_join = nullptr;
    static int s_nsm = 0;
    if (!s_side) {
        cudaStreamCreateWithFlags(&s_side, cudaStreamNonBlocking);
        cudaEventCreateWithFlags(&s_fork, cudaEventDisableTiming);
        cudaEventCreateWithFlags(&s_join, cudaEventDisableTiming);
        cudaDeviceGetAttribute(&s_nsm, cudaDevAttrMultiProcessorCount, 0);
        if (s_nsm <= 0) s_nsm = 148;
    }

    int node_blocks = (NNODES + 255) / 256;
    int edge_blocks = (NEDGES + 255) / 256;

    const int smem_dual128 = (128 * 68) * 4 * 6;                      // 208896
    const int smem_dual32  = (128 * 68) * 4 * 4 + (128 * 20) * 4 * 2; // 159744
    cudaFuncSetAttribute(gemm_dual_pers<128>, cudaFuncAttributeMaxDynamicSharedMemorySize, smem_dual128);
    cudaFuncSetAttribute(gemm_dual_pers<32>,  cudaFuncAttributeMaxDynamicSharedMemorySize, smem_dual32);

    const int M = NNODES;
    const int nchunks = (M + 127) / 128;   // 391
    int attn_blocks = (NNODES + 7) / 8;

    // fork: CSR build chain on side stream, concurrent with layer-0 GEMM
    cudaEventRecord(s_fork, 0);
    cudaStreamWaitEvent(s_side, s_fork, 0);

    detect_kernel<<<1, 256, 0, s_side>>>((const unsigned int*)ei);
    zero_deg_kernel<<<node_blocks, 256, 0, s_side>>>();
    decode_hist_kernel<<<(NEDGES + 255) / 256, 256, 0, s_side>>>(ei);
    scan1_kernel<<<SCAN_BLOCKS, 256, 0, s_side>>>();
    scan2_kernel<<<1, 256, 0, s_side>>>();
    scan3_kernel<<<node_blocks, 256, 0, s_side>>>();
    scatter_kernel<<<edge_blocks, 256, 0, s_side>>>();

    // layer-0 GEMM on main stream (independent of CSR)
    gemm_dual_pers<128><<<s_nsm, 256, smem_dual128>>>(
        x, 0, W[0], linb[0], sW[0], sb[0], M, nchunks);

    // join before attention needs the CSR
    cudaEventRecord(s_join, s_side);
    cudaStreamWaitEvent(0, s_join, 0);

    attn_kernel<<<attn_blocks, 256>>>(att[0], bias[0], 0, (float*)d_out);

    for (int l = 1; l < 3; l++) {
        if (l < 2)
            gemm_dual_pers<128><<<s_nsm, 256, smem_dual128>>>(
                x, 1, W[l], linb[l], sW[l], sb[l], M, nchunks);
        else
            gemm_dual_pers<32><<<s_nsm, 256, smem_dual32>>>(
                x, 1, W[l], linb[l], sW[l], sb[l], M, nchunks);

        attn_kernel<<<attn_blocks, 256>>>(att[l], bias[l], (l == 2) ? 1 : 0,
                                          (float*)d_out);
    }
}